// round 1
// baseline (speedup 1.0000x reference)
#include <cuda_runtime.h>
#include <math.h>

// Problem constants
#define Bc 8
#define Nc 32
#define Tc 32
#define Dc 4
#define Kc 2
#define Hc 256
#define Pc 4
#define Ec 992            // N*(N-1)
#define TGc 8             // T/P
#define BTc 64            // B*TG
#define ROWS_E (BTc*Ec)   // 63488  (divisible by 128)
#define ROWS_N (BTc*Nc)   // 2048

// Output layout (float32):
//   pred_all (B,N,T-1,D)          at 0          size 31744
//   rel_out  (B,E,K)              at 31744      size 15872
//   hooks    (P*TG, B, E, H)      at 47616      size 65011712
#define SZ_PRED (Bc*Nc*(Tc-1)*Dc)
#define OFF_REL SZ_PRED
#define SZ_REL (Bc*Ec*Kc)
#define OFF_HOOK (OFF_REL + SZ_REL)

// Scratch (static device globals; no allocation)
__device__ float g_edges[Ec*Kc];          // softmaxed edge weights
__device__ float g_last[BTc*Nc*Dc];       // current node states (B,Tg,N,D)
__device__ float g_premsg[ROWS_E*8];      // per-edge [send(4), recv(4)]
__device__ float g_msum[(size_t)ROWS_E*Hc]; // summed messages per edge (62MB)

// ---------------------------------------------------------------------------
// Setup: gumbel-softmax edges, rel_out broadcast, last init
// ---------------------------------------------------------------------------
__global__ void k_setup(const float* __restrict__ rel_graph,
                        const float* __restrict__ gumbel,
                        const float* __restrict__ inputs,
                        float* __restrict__ out)
{
    int i = blockIdx.x * blockDim.x + threadIdx.x;
    int stride = gridDim.x * blockDim.x;

    if (i < Ec) {
        float l0 = (rel_graph[2*i]   + gumbel[2*i])   * 2.0f;  // / TAU(0.5)
        float l1 = (rel_graph[2*i+1] + gumbel[2*i+1]) * 2.0f;
        float m  = fmaxf(l0, l1);
        float e0 = expf(l0 - m), e1 = expf(l1 - m);
        float inv = 1.0f / (e0 + e1);
        g_edges[2*i]   = e0 * inv;
        g_edges[2*i+1] = e1 * inv;
    }
    // rel_out[b,e,k] = rel_graph[e,k]
    for (int j = i; j < Bc*Ec*Kc; j += stride)
        out[OFF_REL + j] = rel_graph[j % (Ec*Kc)];
    // last[b,tg,n,d] = inputs[b,n,tg*P,d]
    for (int j = i; j < BTc*Nc*Dc; j += stride) {
        int d  = j & 3;
        int n  = (j >> 2) & 31;
        int bt = j >> 7;
        int b  = bt >> 3, tg = bt & 7;
        g_last[j] = inputs[((b*Nc + n)*Tc + tg*Pc)*Dc + d];
    }
}

// ---------------------------------------------------------------------------
// Per-edge input gather: premsg[row] = [last[s], last[r]]
// ---------------------------------------------------------------------------
__global__ void k_premsg()
{
    int row = blockIdx.x * blockDim.x + threadIdx.x;
    if (row >= ROWS_E) return;
    int e  = row % Ec;
    int bt = row / Ec;
    int r  = e / (Nc-1);
    int j  = e % (Nc-1);
    int s  = j + (j >= r);
    float4 a = *(const float4*)(g_last + (bt*Nc + s)*Dc);
    float4 b = *(const float4*)(g_last + (bt*Nc + r)*Dc);
    float4* o = (float4*)(g_premsg + (size_t)row*8);
    o[0] = a; o[1] = b;
}

// ---------------------------------------------------------------------------
// Edge MLP: fused layer1(on-the-fly) + layer2 GEMM + edge scale + msum + hook
// M=63488 (496 tiles of 128), N=256 (2 tiles of 128), Kdim=256
// ---------------------------------------------------------------------------
__global__ void __launch_bounds__(256) k_edge(
    const float* __restrict__ W1, const float* __restrict__ b1,
    const float* __restrict__ W2, const float* __restrict__ b2,
    float* __restrict__ out, int step)
{
    __shared__ float Ps[128][8];      // premsg tile
    __shared__ float Ev[128][2];      // edge weights per row
    __shared__ float W1s[8][256];
    __shared__ float b1s[256];
    __shared__ float b2s[128];
    __shared__ float As[16][132];     // A tile (transposed: [kchunk][m])
    __shared__ float Bs[16][132];     // B tile [kchunk][n]

    int tid   = threadIdx.x;
    int mbase = blockIdx.x * 128;
    int nbase = blockIdx.y * 128;
    int tx = tid & 15;   // col group: cols tx*8..tx*8+7
    int ty = tid >> 4;   // row group: rows ty*8..ty*8+7

    // Load premsg tile + edge weights
    {
        int rr = tid >> 1, h = tid & 1;
        *(float4*)(&Ps[rr][h*4]) =
            *(const float4*)(g_premsg + (size_t)(mbase + rr)*8 + h*4);
        if (tid < 128) {
            int e = (mbase + tid) % Ec;
            Ev[tid][0] = g_edges[2*e];
            Ev[tid][1] = g_edges[2*e+1];
        }
    }

    for (int k = 0; k < Kc; k++) {
        __syncthreads();   // guard reuse of W1s/b1s/b2s and first-iter Ps
        // load W1[k], b1[k], b2[k] slice
        {
            const float4* w1p = (const float4*)(W1 + k*2048);
            ((float4*)&W1s[0][0])[tid]       = w1p[tid];
            ((float4*)&W1s[0][0])[tid + 256] = w1p[tid + 256];
            b1s[tid] = b1[k*256 + tid];
            if (tid < 128) b2s[tid] = b2[k*256 + nbase + tid];
        }
        __syncthreads();

        float acc[8][8];
        #pragma unroll
        for (int r2 = 0; r2 < 8; r2++)
            #pragma unroll
            for (int c = 0; c < 8; c++) acc[r2][c] = 0.f;

        for (int kk = 0; kk < Hc; kk += 16) {
            // stage B tile: W2[k][kk+i][nbase+j]
            {
                int i = tid >> 4;
                int j = (tid & 15) * 8;
                const float* src = W2 + ((size_t)(k*Hc + kk + i))*Hc + nbase + j;
                *(float4*)(&Bs[i][j])   = *(const float4*)(src);
                *(float4*)(&Bs[i][j+4]) = *(const float4*)(src + 4);
            }
            // generate A tile: m1 = relu(premsg @ W1[k] + b1[k])
            {
                int i  = tid & 15;
                int m0 = (tid >> 4) * 8;
                float w[8];
                #pragma unroll
                for (int d = 0; d < 8; d++) w[d] = W1s[d][kk + i];
                float bb = b1s[kk + i];
                float vbuf[8];
                #pragma unroll
                for (int mm = 0; mm < 8; mm++) {
                    float4 p0 = *(const float4*)(&Ps[m0+mm][0]);
                    float4 p1 = *(const float4*)(&Ps[m0+mm][4]);
                    float v = bb;
                    v += p0.x*w[0]; v += p0.y*w[1]; v += p0.z*w[2]; v += p0.w*w[3];
                    v += p1.x*w[4]; v += p1.y*w[5]; v += p1.z*w[6]; v += p1.w*w[7];
                    vbuf[mm] = fmaxf(v, 0.f);
                }
                *(float4*)(&As[i][m0])   = *(float4*)(vbuf);
                *(float4*)(&As[i][m0+4]) = *(float4*)(vbuf+4);
            }
            __syncthreads();
            #pragma unroll
            for (int i = 0; i < 16; i++) {
                float a[8], bv[8];
                *(float4*)(a)    = *(const float4*)(&As[i][ty*8]);
                *(float4*)(a+4)  = *(const float4*)(&As[i][ty*8+4]);
                *(float4*)(bv)   = *(const float4*)(&Bs[i][tx*8]);
                *(float4*)(bv+4) = *(const float4*)(&Bs[i][tx*8+4]);
                #pragma unroll
                for (int r2 = 0; r2 < 8; r2++)
                    #pragma unroll
                    for (int c = 0; c < 8; c++)
                        acc[r2][c] += a[r2] * bv[c];
            }
            __syncthreads();
        }

        // epilogue: bias, relu, edge scale; k=0: store partial, k=1: sum + hook
        #pragma unroll
        for (int r2 = 0; r2 < 8; r2++) {
            int lm   = ty*8 + r2;
            int grow = mbase + lm;
            float esc = Ev[lm][k];
            float vals[8];
            #pragma unroll
            for (int c = 0; c < 8; c++)
                vals[c] = fmaxf(acc[r2][c] + b2s[tx*8 + c], 0.f) * esc;
            float* mp = g_msum + (size_t)grow*Hc + nbase + tx*8;
            if (k == 0) {
                *(float4*)(mp)   = *(float4*)(vals);
                *(float4*)(mp+4) = *(float4*)(vals+4);
            } else {
                float4 o0 = *(float4*)(mp), o1 = *(float4*)(mp+4);
                o0.x += vals[0]; o0.y += vals[1]; o0.z += vals[2]; o0.w += vals[3];
                o1.x += vals[4]; o1.y += vals[5]; o1.z += vals[6]; o1.w += vals[7];
                *(float4*)(mp)   = o0;
                *(float4*)(mp+4) = o1;
                // hook = m_{k=1} * e1, layout (P*TG, B, E, H)
                int e  = grow % Ec;
                int bt = grow / Ec;
                int b  = bt >> 3, tg = bt & 7;
                size_t hr = ((size_t)((step*TGc + tg)*Bc + b)*Ec + e);
                float* hp = out + OFF_HOOK + hr*Hc + nbase + tx*8;
                *(float4*)(hp)   = *(float4*)(vals);
                *(float4*)(hp+4) = *(float4*)(vals+4);
            }
        }
    }
}

// ---------------------------------------------------------------------------
// Node MLP: fused agg + 3-layer MLP + residual + pred write + last update
// grid = 128 blocks: (bt, node-half of 16)
// ---------------------------------------------------------------------------
__global__ void __launch_bounds__(256) k_node(
    const float* __restrict__ Wo1, const float* __restrict__ bo1,
    const float* __restrict__ Wo2, const float* __restrict__ bo2,
    const float* __restrict__ Wo3, const float* __restrict__ bo3,
    float* __restrict__ out, int step)
{
    __shared__ float augS[16][264];   // [n][0..3]=last, [4..259]=agg / h2
    __shared__ float h1S[16][264];
    __shared__ float lastS[16][4];
    __shared__ float wo3S[Hc*Dc];

    int tid = threadIdx.x;
    int bt  = blockIdx.x >> 1;
    int nh  = blockIdx.x & 1;
    int n0  = nh * 16;

    for (int i = tid; i < Hc*Dc; i += 256) wo3S[i] = Wo3[i];
    if (tid < 64) {
        int n = tid >> 2, d = tid & 3;
        float v = g_last[(bt*Nc + n0 + n)*Dc + d];
        lastS[n][d] = v;
        augS[n][d]  = v;
    }
    // agg[n][h] = sum_{j<31} msum[bt, n*31+j][h]
    {
        int h = tid;
        for (int n = 0; n < 16; n++) {
            const float* mp = g_msum + ((size_t)bt*Ec + (size_t)(n0+n)*(Nc-1))*Hc + h;
            float s = 0.f;
            #pragma unroll 8
            for (int j = 0; j < Nc-1; j++) s += mp[(size_t)j*Hc];
            augS[n][4 + h] = s;
        }
    }
    __syncthreads();

    int ty = tid >> 5;        // 0..7 -> rows ty*2, ty*2+1
    int tx = tid & 31;        // cols tx*8..tx*8+7
    int r0 = ty*2, r1 = r0 + 1;

    // Layer 1: aug(260) @ Wo1 -> relu -> h1S
    {
        float acc0[8], acc1[8];
        #pragma unroll
        for (int c = 0; c < 8; c++) { acc0[c] = 0.f; acc1[c] = 0.f; }
        #pragma unroll 4
        for (int j = 0; j < Dc + Hc; j++) {
            float a0 = augS[r0][j];
            float a1 = augS[r1][j];
            const float4* wp = (const float4*)(Wo1 + j*Hc + tx*8);
            float w[8];
            *(float4*)(w)   = wp[0];
            *(float4*)(w+4) = wp[1];
            #pragma unroll
            for (int c = 0; c < 8; c++) { acc0[c] += a0*w[c]; acc1[c] += a1*w[c]; }
        }
        #pragma unroll
        for (int c = 0; c < 8; c++) {
            float bb = bo1[tx*8 + c];
            h1S[r0][tx*8 + c] = fmaxf(acc0[c] + bb, 0.f);
            h1S[r1][tx*8 + c] = fmaxf(acc1[c] + bb, 0.f);
        }
    }
    __syncthreads();

    // Layer 2: h1(256) @ Wo2 -> relu -> augS[:,4..]
    {
        float acc0[8], acc1[8];
        #pragma unroll
        for (int c = 0; c < 8; c++) { acc0[c] = 0.f; acc1[c] = 0.f; }
        #pragma unroll 4
        for (int j = 0; j < Hc; j++) {
            float a0 = h1S[r0][j];
            float a1 = h1S[r1][j];
            const float4* wp = (const float4*)(Wo2 + j*Hc + tx*8);
            float w[8];
            *(float4*)(w)   = wp[0];
            *(float4*)(w+4) = wp[1];
            #pragma unroll
            for (int c = 0; c < 8; c++) { acc0[c] += a0*w[c]; acc1[c] += a1*w[c]; }
        }
        #pragma unroll
        for (int c = 0; c < 8; c++) {
            float bb = bo2[tx*8 + c];
            augS[r0][4 + tx*8 + c] = fmaxf(acc0[c] + bb, 0.f);
            augS[r1][4 + tx*8 + c] = fmaxf(acc1[c] + bb, 0.f);
        }
    }
    __syncthreads();

    // Layer 3 (256->4) + residual + writes
    if (tid < 64) {
        int n = tid >> 2, d = tid & 3;
        float v = bo3[d];
        #pragma unroll 8
        for (int c = 0; c < Hc; c++) v += augS[n][4 + c] * wo3S[c*Dc + d];
        float nl = lastS[n][d] + v;
        int gn = n0 + n;
        g_last[(bt*Nc + gn)*Dc + d] = nl;
        int b = bt >> 3, tg = bt & 7;
        int t = tg*Pc + step;
        if (t < Tc - 1)
            out[((b*Nc + gn)*(Tc-1) + t)*Dc + d] = nl;
    }
}

// ---------------------------------------------------------------------------
extern "C" void kernel_launch(void* const* d_in, const int* in_sizes, int n_in,
                              void* d_out, int out_size)
{
    const float* inputs    = (const float*)d_in[0];
    const float* rel_graph = (const float*)d_in[1];
    const float* W1  = (const float*)d_in[2];
    const float* b1  = (const float*)d_in[3];
    const float* W2  = (const float*)d_in[4];
    const float* b2  = (const float*)d_in[5];
    const float* Wo1 = (const float*)d_in[6];
    const float* bo1 = (const float*)d_in[7];
    const float* Wo2 = (const float*)d_in[8];
    const float* bo2 = (const float*)d_in[9];
    const float* Wo3 = (const float*)d_in[10];
    const float* bo3 = (const float*)d_in[11];
    // d_in[12], d_in[13]: rel_rec/rel_send onehots — structure used analytically
    const float* gumbel = (const float*)d_in[14];
    float* out = (float*)d_out;

    k_setup<<<64, 256>>>(rel_graph, gumbel, inputs, out);
    for (int p = 0; p < Pc; p++) {
        k_premsg<<<(ROWS_E + 255)/256, 256>>>();
        dim3 g(ROWS_E/128, Hc/128);
        k_edge<<<g, 256>>>(W1, b1, W2, b2, out, p);
        k_node<<<128, 256>>>(Wo1, bo1, Wo2, bo2, Wo3, bo3, out, p);
    }
}

// round 4
// speedup vs baseline: 1.4083x; 1.4083x over previous
#include <cuda_runtime.h>
#include <cuda_fp16.h>
#include <stdint.h>
#include <math.h>

// Problem constants
#define Bc 8
#define Nc 32
#define Tc 32
#define Dc 4
#define Kc 2
#define Hc 256
#define Pc 4
#define Ec 992            // N*(N-1)
#define TGc 8             // T/P
#define BTc 64            // B*TG
#define ROWS_E (BTc*Ec)   // 63488

// Output layout (float32)
#define SZ_PRED (Bc*Nc*(Tc-1)*Dc)
#define OFF_REL SZ_PRED
#define SZ_REL (Bc*Ec*Kc)
#define OFF_HOOK (OFF_REL + SZ_REL)

// Device scratch (no allocation)
__device__ float g_edges[Ec*Kc];
__device__ float g_last[BTc*Nc*Dc];
__device__ float g_premsg[ROWS_E*8];
__device__ float g_agg[BTc*Nc*Hc];      // 2 MB aggregated messages per node
__device__ uint4 g_W2h[16384];          // W2^T fp16 [expert][n][k], XOR-swizzled rows (256 KB)

// ---------------------------------------------------------------------------
// smem layout for k_edge (dynamic)
#define SMEM_A    0            // A fp16, both experts: 2 x 128 rows x 512B = 131072
#define SMEM_B    131072       // B fp16 half-tile 128 rows x 512B = 65536; reused as Ms 128x128 f32
#define SMEM_PS   196608       // premsg 128x8 f32      4096
#define SMEM_W1   200704       // W1 both experts f32  16384
#define SMEM_B1   217088       // b1 both               2048
#define SMEM_B2   219136       // b2 both               2048
#define SMEM_EV   221184       // edge weights 128x2    1024
#define SMEM_GID  222208       // group id per row       512
#define SMEM_GEND 222720       // group-end flag         512
#define SMEM_TOTAL 223232

static __device__ __forceinline__ uint32_t smem_u32(const void* p) {
    uint32_t a;
    asm("{ .reg .u64 t; cvta.to.shared.u64 t, %1; cvt.u32.u64 %0, t; }" : "=r"(a) : "l"(p));
    return a;
}
#define LDMX4(r0,r1,r2,r3,addr) \
    asm volatile("ldmatrix.sync.aligned.m8n8.x4.shared.b16 {%0,%1,%2,%3}, [%4];" \
        : "=r"(r0), "=r"(r1), "=r"(r2), "=r"(r3) : "r"(addr))
#define MMA16816(c,a0,a1,a2,a3,b0,b1) \
    asm volatile("mma.sync.aligned.m16n8k16.row.col.f32.f16.f16.f32 " \
        "{%0,%1,%2,%3}, {%4,%5,%6,%7}, {%8,%9}, {%0,%1,%2,%3};" \
        : "+f"((c)[0]), "+f"((c)[1]), "+f"((c)[2]), "+f"((c)[3]) \
        : "r"(a0), "r"(a1), "r"(a2), "r"(a3), "r"(b0), "r"(b1))

// A/B smem element (row, k): row*512 + ((k/8 ^ (row&7))*16) + (k&7)*2
static __device__ __forceinline__ int sw_off(int row, int kchunk) {
    return row*512 + ((kchunk ^ (row & 7)) << 4);
}

// ---------------------------------------------------------------------------
__global__ void k_setup(const float* __restrict__ rel_graph,
                        const float* __restrict__ gumbel,
                        const float* __restrict__ inputs,
                        float* __restrict__ out)
{
    int i = blockIdx.x * blockDim.x + threadIdx.x;
    int stride = gridDim.x * blockDim.x;
    if (i < Ec) {
        float l0 = (rel_graph[2*i]   + gumbel[2*i])   * 2.0f;
        float l1 = (rel_graph[2*i+1] + gumbel[2*i+1]) * 2.0f;
        float m  = fmaxf(l0, l1);
        float e0 = expf(l0 - m), e1 = expf(l1 - m);
        float inv = 1.0f / (e0 + e1);
        g_edges[2*i]   = e0 * inv;
        g_edges[2*i+1] = e1 * inv;
    }
    for (int j = i; j < Bc*Ec*Kc; j += stride)
        out[OFF_REL + j] = rel_graph[j % (Ec*Kc)];
    for (int j = i; j < BTc*Nc*Dc; j += stride) {
        int d  = j & 3;
        int n  = (j >> 2) & 31;
        int bt = j >> 7;
        int b  = bt >> 3, tg = bt & 7;
        g_last[j] = inputs[((b*Nc + n)*Tc + tg*Pc)*Dc + d];
    }
}

// ---------------------------------------------------------------------------
// Prep: W2^T -> fp16, [expert][n][k] rows XOR-swizzled (for ldmatrix B frags)
// ---------------------------------------------------------------------------
__global__ void k_prep(const float* __restrict__ W2)
{
    int g = blockIdx.x * blockDim.x + threadIdx.x;   // 0..16383
    if (g >= 16384) return;
    int ex  = g >> 13;
    int rem = g & 8191;
    int n   = rem >> 5;         // 0..255
    int kg  = (rem & 31) * 8;   // 0..248
    float w[8];
    #pragma unroll
    for (int j = 0; j < 8; j++) w[j] = W2[ex*65536 + (kg + j)*256 + n];
    uint4 pk;
    __half2 h0 = __floats2half2_rn(w[0], w[1]);
    __half2 h1 = __floats2half2_rn(w[2], w[3]);
    __half2 h2 = __floats2half2_rn(w[4], w[5]);
    __half2 h3 = __floats2half2_rn(w[6], w[7]);
    pk.x = *(uint32_t*)&h0; pk.y = *(uint32_t*)&h1;
    pk.z = *(uint32_t*)&h2; pk.w = *(uint32_t*)&h3;
    *(uint4*)((char*)g_W2h + ex*131072 + sw_off(n, kg >> 3)) = pk;
}

// ---------------------------------------------------------------------------
__global__ void k_premsg()
{
    int row = blockIdx.x * blockDim.x + threadIdx.x;
    if (row < ROWS_E) {
        int e  = row % Ec;
        int bt = row / Ec;
        int r  = e / (Nc-1);
        int j  = e % (Nc-1);
        int s  = j + (j >= r);
        float4 a = *(const float4*)(g_last + (bt*Nc + s)*Dc);
        float4 b = *(const float4*)(g_last + (bt*Nc + r)*Dc);
        float4* o = (float4*)(g_premsg + (size_t)row*8);
        o[0] = a; o[1] = b;
    }
    int stride = gridDim.x * blockDim.x;
    for (int j = row; j < BTc*Nc*Hc; j += stride) g_agg[j] = 0.f;
}

// ---------------------------------------------------------------------------
// Edge MLP via mma.sync fp16 tensor cores.
// ---------------------------------------------------------------------------
__global__ void __launch_bounds__(256) k_edge(
    const float* __restrict__ W1, const float* __restrict__ b1,
    const float* __restrict__ b2, float* __restrict__ out, int step)
{
    extern __shared__ __align__(1024) char sm[];
    uint32_t sb = smem_u32(sm);
    int tid = threadIdx.x, wid = tid >> 5, lane = tid & 31;
    int mbase = blockIdx.x * 128;

    // ---- stage loads ----
    {
        int rr = tid >> 1, h = tid & 1;
        *(float4*)(sm + SMEM_PS + (rr*8 + h*4)*4) =
            *(const float4*)(g_premsg + (size_t)(mbase + rr)*8 + h*4);
    }
    {
        const float4* w1p = (const float4*)W1;
        float4* dst = (float4*)(sm + SMEM_W1);
        #pragma unroll
        for (int i = 0; i < 4; i++) dst[tid + i*256] = w1p[tid + i*256];
    }
    {
        float* d1 = (float*)(sm + SMEM_B1);
        float* d2 = (float*)(sm + SMEM_B2);
        d1[tid] = b1[tid]; d1[tid+256] = b1[tid+256];
        d2[tid] = b2[tid]; d2[tid+256] = b2[tid+256];
    }
    if (tid < 128) {
        int grow = mbase + tid;
        int e = grow % Ec, bt = grow / Ec;
        ((float*)(sm + SMEM_EV))[2*tid]   = g_edges[2*e];
        ((float*)(sm + SMEM_EV))[2*tid+1] = g_edges[2*e+1];
        ((int*)(sm + SMEM_GID))[tid]  = bt*Nc + e/(Nc-1);
        ((int*)(sm + SMEM_GEND))[tid] = (e % (Nc-1) == (Nc-2)) ? 1 : 0;
    }
    __syncthreads();

    // ---- A build: both experts, relu(premsg @ W1_e + b1_e) -> fp16 swizzled ----
    {
        int m  = tid >> 1;
        int kh = (tid & 1) * 128;
        float p[8];
        const float* Pr = (const float*)(sm + SMEM_PS) + m*8;
        #pragma unroll
        for (int d = 0; d < 8; d++) p[d] = Pr[d];
        for (int e = 0; e < Kc; e++) {
            const float* W1k = (const float*)(sm + SMEM_W1) + e*2048;
            const float* b1k = (const float*)(sm + SMEM_B1) + e*256;
            #pragma unroll 4
            for (int kg = 0; kg < 16; kg++) {
                int k0 = kh + kg*8;
                float v[8];
                #pragma unroll
                for (int j = 0; j < 8; j++) v[j] = b1k[k0 + j];
                #pragma unroll
                for (int d = 0; d < 8; d++) {
                    const float* wr = W1k + d*256 + k0;
                    #pragma unroll
                    for (int j = 0; j < 8; j++) v[j] += p[d] * wr[j];
                }
                uint4 pk;
                __half2 h0 = __floats2half2_rn(fmaxf(v[0],0.f), fmaxf(v[1],0.f));
                __half2 h1 = __floats2half2_rn(fmaxf(v[2],0.f), fmaxf(v[3],0.f));
                __half2 h2 = __floats2half2_rn(fmaxf(v[4],0.f), fmaxf(v[5],0.f));
                __half2 h3 = __floats2half2_rn(fmaxf(v[6],0.f), fmaxf(v[7],0.f));
                pk.x = *(uint32_t*)&h0; pk.y = *(uint32_t*)&h1;
                pk.z = *(uint32_t*)&h2; pk.w = *(uint32_t*)&h3;
                *(uint4*)(sm + SMEM_A + e*65536 + sw_off(m, k0 >> 3)) = pk;
            }
        }
    }

    // warp tiling: 4 row-warps x 2 col-warps over (m128, n128-half)
    int m0w = (wid & 3) * 32;
    int n0w = (wid >> 2) * 64;
    int lane4 = lane & 3, lrow = lane >> 2;

    // per-row epilogue constants
    float e0v[4], e1v[4]; size_t hookbase[4]; int rowlut[4];
    #pragma unroll
    for (int q = 0; q < 4; q++) {
        int mi = q >> 1, rg = q & 1;
        int row = m0w + mi*16 + rg*8 + lrow;
        rowlut[q] = row;
        e0v[q] = ((const float*)(sm + SMEM_EV))[2*row];
        e1v[q] = ((const float*)(sm + SMEM_EV))[2*row + 1];
        int grow = mbase + row;
        int eG = grow % Ec, btG = grow / Ec;
        int bb = btG >> 3, tg = btG & 7;
        hookbase[q] = (size_t)(((step*TGc + tg)*Bc + bb)*Ec + eG) * Hc;
    }

    // precompute ldmatrix row components
    uint32_t aRow[2], bRow[4];
    #pragma unroll
    for (int mi = 0; mi < 2; mi++) {
        int row = m0w + mi*16 + (lane & 15);
        aRow[mi] = row*512 + ((row & 7) << 4);   // fold XOR base: chunk^(row&7) -> (chunk<<4) ^ ((row&7)<<4)
    }
    #pragma unroll
    for (int njp = 0; njp < 4; njp++) {
        int row = n0w + njp*16 + ((lane >> 4) << 3) + (lane & 7);
        bRow[njp] = row*512 + ((row & 7) << 4);
    }
    uint32_t aChunkSel = (lane >> 4);        // +0/+1 chunk
    uint32_t bChunkSel = ((lane >> 3) & 1);

    const float* b2s = (const float*)(sm + SMEM_B2);
    const int* gid  = (const int*)(sm + SMEM_GID);
    const int* gend = (const int*)(sm + SMEM_GEND);

    for (int nhalf = 0; nhalf < 2; nhalf++) {
        float acc0[2][8][4];
        float acc1[2][8][4];

        for (int e = 0; e < Kc; e++) {
            // load B half-tile for this expert (linear 64 KB, swizzle pre-baked)
            {
                uint4* Bd = (uint4*)(sm + SMEM_B);
                const uint4* src = g_W2h + e*8192 + nhalf*4096;
                #pragma unroll
                for (int i = 0; i < 16; i++) Bd[tid + i*256] = src[tid + i*256];
            }
            __syncthreads();

            float (*acc)[8][4] = (e == 0) ? acc0 : acc1;
            #pragma unroll
            for (int mi = 0; mi < 2; mi++)
                #pragma unroll
                for (int nj = 0; nj < 8; nj++)
                    #pragma unroll
                    for (int c = 0; c < 4; c++) acc[mi][nj][c] = 0.f;

            uint32_t aBase = sb + SMEM_A + e*65536;
            uint32_t bBase = sb + SMEM_B;
            #pragma unroll 2
            for (int kc = 0; kc < 16; kc++) {
                uint32_t af[2][4], bf[4][4];
                #pragma unroll
                for (int mi = 0; mi < 2; mi++) {
                    uint32_t chunk = kc*2 + aChunkSel;
                    uint32_t addr = aBase + (aRow[mi] ^ (chunk << 4));
                    LDMX4(af[mi][0], af[mi][1], af[mi][2], af[mi][3], addr);
                }
                #pragma unroll
                for (int njp = 0; njp < 4; njp++) {
                    uint32_t chunk = kc*2 + bChunkSel;
                    uint32_t addr = bBase + (bRow[njp] ^ (chunk << 4));
                    LDMX4(bf[njp][0], bf[njp][1], bf[njp][2], bf[njp][3], addr);
                }
                #pragma unroll
                for (int mi = 0; mi < 2; mi++)
                    #pragma unroll
                    for (int njp = 0; njp < 4; njp++) {
                        MMA16816(acc[mi][njp*2],   af[mi][0], af[mi][1], af[mi][2], af[mi][3],
                                 bf[njp][0], bf[njp][1]);
                        MMA16816(acc[mi][njp*2+1], af[mi][0], af[mi][1], af[mi][2], af[mi][3],
                                 bf[njp][2], bf[njp][3]);
                    }
            }
            __syncthreads();   // all warps done reading B before it is overwritten

            if (e == 0) {
                // fold expert-0 epilogue into registers: acc0 <- relu(acc0+b2_0)*e0
                #pragma unroll
                for (int mi = 0; mi < 2; mi++)
                    #pragma unroll
                    for (int nj = 0; nj < 8; nj++) {
                        int colg = nhalf*128 + n0w + nj*8 + lane4*2;
                        float ba = b2s[colg], bbv = b2s[colg + 1];
                        #pragma unroll
                        for (int rg = 0; rg < 2; rg++) {
                            int q = mi*2 + rg;
                            acc0[mi][nj][rg*2]   = fmaxf(acc0[mi][nj][rg*2]   + ba,  0.f) * e0v[q];
                            acc0[mi][nj][rg*2+1] = fmaxf(acc0[mi][nj][rg*2+1] + bbv, 0.f) * e0v[q];
                        }
                    }
            }
        }

        // ---- epilogue: expert1 relu/scale, hooks, msv -> Ms smem ----
        #pragma unroll
        for (int mi = 0; mi < 2; mi++)
            #pragma unroll
            for (int nj = 0; nj < 8; nj++) {
                int colh = n0w + nj*8 + lane4*2;
                int colg = nhalf*128 + colh;
                float ba = b2s[256 + colg], bbv = b2s[256 + colg + 1];
                #pragma unroll
                for (int rg = 0; rg < 2; rg++) {
                    int q = mi*2 + rg;
                    float h0 = fmaxf(acc1[mi][nj][rg*2]   + ba,  0.f) * e1v[q];
                    float h1 = fmaxf(acc1[mi][nj][rg*2+1] + bbv, 0.f) * e1v[q];
                    float m0 = acc0[mi][nj][rg*2]   + h0;
                    float m1 = acc0[mi][nj][rg*2+1] + h1;
                    *(float2*)(out + OFF_HOOK + hookbase[q] + colg) = make_float2(h0, h1);
                    *(float2*)(sm + SMEM_B + rowlut[q]*512 + colh*4) = make_float2(m0, m1);
                }
            }
        __syncthreads();

        // ---- segmented reduction over recv-node groups -> g_agg atomics ----
        {
            int col = tid & 127;
            int rh  = tid >> 7;
            int rbeg = rh * 64, rend = rbeg + 64;
            const float* Msf = (const float*)(sm + SMEM_B);
            float accv = 0.f;
            for (int r = rbeg; r < rend; r++) {
                accv += Msf[r*128 + col];
                if (gend[r]) {
                    atomicAdd(g_agg + (size_t)gid[r]*Hc + nhalf*128 + col, accv);
                    accv = 0.f;
                }
            }
            if (!gend[rend-1])
                atomicAdd(g_agg + (size_t)gid[rend-1]*Hc + nhalf*128 + col, accv);
        }
        __syncthreads();
    }
}

// ---------------------------------------------------------------------------
// Node MLP
// ---------------------------------------------------------------------------
__global__ void __launch_bounds__(256) k_node(
    const float* __restrict__ Wo1, const float* __restrict__ bo1,
    const float* __restrict__ Wo2, const float* __restrict__ bo2,
    const float* __restrict__ Wo3, const float* __restrict__ bo3,
    float* __restrict__ out, int step)
{
    __shared__ float augS[16][264];
    __shared__ float h1S[16][264];
    __shared__ float lastS[16][4];
    __shared__ float wo3S[Hc*Dc];

    int tid = threadIdx.x;
    int bt  = blockIdx.x >> 1;
    int nh  = blockIdx.x & 1;
    int n0  = nh * 16;

    for (int i = tid; i < Hc*Dc; i += 256) wo3S[i] = Wo3[i];
    if (tid < 64) {
        int n = tid >> 2, d = tid & 3;
        float v = g_last[(bt*Nc + n0 + n)*Dc + d];
        lastS[n][d] = v;
        augS[n][d]  = v;
    }
    {
        int h = tid;
        #pragma unroll 4
        for (int n = 0; n < 16; n++)
            augS[n][4 + h] = g_agg[((size_t)(bt*Nc + n0 + n))*Hc + h];
    }
    __syncthreads();

    int ty = tid >> 5;
    int tx = tid & 31;
    int r0 = ty*2, r1 = r0 + 1;

    // Layer 1
    {
        float acc0[8], acc1[8];
        #pragma unroll
        for (int c = 0; c < 8; c++) { acc0[c] = 0.f; acc1[c] = 0.f; }
        #pragma unroll 4
        for (int j = 0; j < Dc + Hc; j++) {
            float a0 = augS[r0][j];
            float a1 = augS[r1][j];
            const float4* wp = (const float4*)(Wo1 + j*Hc + tx*8);
            float w[8];
            *(float4*)(w)   = wp[0];
            *(float4*)(w+4) = wp[1];
            #pragma unroll
            for (int c = 0; c < 8; c++) { acc0[c] += a0*w[c]; acc1[c] += a1*w[c]; }
        }
        #pragma unroll
        for (int c = 0; c < 8; c++) {
            float bb = bo1[tx*8 + c];
            h1S[r0][tx*8 + c] = fmaxf(acc0[c] + bb, 0.f);
            h1S[r1][tx*8 + c] = fmaxf(acc1[c] + bb, 0.f);
        }
    }
    __syncthreads();

    // Layer 2
    {
        float acc0[8], acc1[8];
        #pragma unroll
        for (int c = 0; c < 8; c++) { acc0[c] = 0.f; acc1[c] = 0.f; }
        #pragma unroll 4
        for (int j = 0; j < Hc; j++) {
            float a0 = h1S[r0][j];
            float a1 = h1S[r1][j];
            const float4* wp = (const float4*)(Wo2 + j*Hc + tx*8);
            float w[8];
            *(float4*)(w)   = wp[0];
            *(float4*)(w+4) = wp[1];
            #pragma unroll
            for (int c = 0; c < 8; c++) { acc0[c] += a0*w[c]; acc1[c] += a1*w[c]; }
        }
        #pragma unroll
        for (int c = 0; c < 8; c++) {
            float bb = bo2[tx*8 + c];
            augS[r0][4 + tx*8 + c] = fmaxf(acc0[c] + bb, 0.f);
            augS[r1][4 + tx*8 + c] = fmaxf(acc1[c] + bb, 0.f);
        }
    }
    __syncthreads();

    // Layer 3 + residual + writes
    if (tid < 64) {
        int n = tid >> 2, d = tid & 3;
        float v = bo3[d];
        #pragma unroll 8
        for (int c = 0; c < Hc; c++) v += augS[n][4 + c] * wo3S[c*Dc + d];
        float nl = lastS[n][d] + v;
        int gn = n0 + n;
        g_last[(bt*Nc + gn)*Dc + d] = nl;
        int b = bt >> 3, tg = bt & 7;
        int t = tg*Pc + step;
        if (t < Tc - 1)
            out[((b*Nc + gn)*(Tc-1) + t)*Dc + d] = nl;
    }
}

// ---------------------------------------------------------------------------
extern "C" void kernel_launch(void* const* d_in, const int* in_sizes, int n_in,
                              void* d_out, int out_size)
{
    const float* inputs    = (const float*)d_in[0];
    const float* rel_graph = (const float*)d_in[1];
    const float* W1  = (const float*)d_in[2];
    const float* b1  = (const float*)d_in[3];
    const float* W2  = (const float*)d_in[4];
    const float* b2  = (const float*)d_in[5];
    const float* Wo1 = (const float*)d_in[6];
    const float* bo1 = (const float*)d_in[7];
    const float* Wo2 = (const float*)d_in[8];
    const float* bo2 = (const float*)d_in[9];
    const float* Wo3 = (const float*)d_in[10];
    const float* bo3 = (const float*)d_in[11];
    const float* gumbel = (const float*)d_in[14];
    float* out = (float*)d_out;

    cudaFuncSetAttribute(k_edge, cudaFuncAttributeMaxDynamicSharedMemorySize, SMEM_TOTAL);

    k_setup<<<64, 256>>>(rel_graph, gumbel, inputs, out);
    k_prep<<<64, 256>>>(W2);
    for (int p = 0; p < Pc; p++) {
        k_premsg<<<(ROWS_E + 255)/256, 256>>>();
        k_edge<<<ROWS_E/128, 256, SMEM_TOTAL>>>(W1, b1, b2, out, p);
        k_node<<<128, 256>>>(Wo1, bo1, Wo2, bo2, Wo3, bo3, out, p);
    }
}

// round 5
// speedup vs baseline: 2.7035x; 1.9197x over previous
#include <cuda_runtime.h>
#include <cuda_fp16.h>
#include <stdint.h>
#include <math.h>

// Problem constants
#define Bc 8
#define Nc 32
#define Tc 32
#define Dc 4
#define Kc 2
#define Hc 256
#define Pc 4
#define Ec 992            // N*(N-1)
#define TGc 8             // T/P
#define BTc 64            // B*TG
#define ROWS_E (BTc*Ec)   // 63488

// Output layout (float32)
#define SZ_PRED (Bc*Nc*(Tc-1)*Dc)
#define OFF_REL SZ_PRED
#define SZ_REL (Bc*Ec*Kc)
#define OFF_HOOK (OFF_REL + SZ_REL)

// Device scratch (no allocation)
__device__ float g_edges[Ec*Kc];
__device__ float g_last[BTc*Nc*Dc];
__device__ float g_premsg[ROWS_E*8];
__device__ float g_agg[BTc*Nc*Hc];      // 2 MB aggregated messages per node
__device__ uint4 g_W2h[16384];          // W2^T fp16 [expert][n][k], XOR-swizzled rows (256 KB)

// ---------------------------------------------------------------------------
// smem layout for k_edge (dynamic)
#define SMEM_A    0            // A fp16, both experts: 2 x 128 rows x 512B = 131072
#define SMEM_B    131072       // B fp16 half-tile 128 rows x 512B = 65536; reused as Ms 128x128 f32
#define SMEM_PS   196608       // premsg 128x8 f32      4096
#define SMEM_W1   200704       // W1 both experts f32  16384
#define SMEM_B1   217088       // b1 both               2048
#define SMEM_B2   219136       // b2 both               2048
#define SMEM_EV   221184       // edge weights 128x2    1024
#define SMEM_GID  222208       // group id per row       512
#define SMEM_GEND 222720       // group-end flag         512
#define SMEM_TOTAL 223232

static __device__ __forceinline__ uint32_t smem_u32(const void* p) {
    uint32_t a;
    asm("{ .reg .u64 t; cvta.to.shared.u64 t, %1; cvt.u32.u64 %0, t; }" : "=r"(a) : "l"(p));
    return a;
}
#define LDMX4(r0,r1,r2,r3,addr) \
    asm volatile("ldmatrix.sync.aligned.m8n8.x4.shared.b16 {%0,%1,%2,%3}, [%4];" \
        : "=r"(r0), "=r"(r1), "=r"(r2), "=r"(r3) : "r"(addr))
#define MMA16816(c,a0,a1,a2,a3,b0,b1) \
    asm volatile("mma.sync.aligned.m16n8k16.row.col.f32.f16.f16.f32 " \
        "{%0,%1,%2,%3}, {%4,%5,%6,%7}, {%8,%9}, {%0,%1,%2,%3};" \
        : "+f"((c)[0]), "+f"((c)[1]), "+f"((c)[2]), "+f"((c)[3]) \
        : "r"(a0), "r"(a1), "r"(a2), "r"(a3), "r"(b0), "r"(b1))

// A/B smem element (row, k): row*512 + ((k/8 ^ (row&7))*16) + (k&7)*2
static __device__ __forceinline__ int sw_off(int row, int kchunk) {
    return row*512 + ((kchunk ^ (row & 7)) << 4);
}

// GEMM pass over one expert's A (aBase) and staged B half-tile (bBase).
// Accumulators passed by reference with compile-time indexing only ->
// guaranteed register residency (NO runtime pointer selection!).
static __device__ __forceinline__ void gemm_pass(
    float (&acc)[2][8][4],
    uint32_t aBase, uint32_t bBase,
    const uint32_t (&aRow)[2], const uint32_t (&bRow)[4],
    uint32_t aChunkSel, uint32_t bChunkSel)
{
    #pragma unroll
    for (int mi = 0; mi < 2; mi++)
        #pragma unroll
        for (int nj = 0; nj < 8; nj++)
            #pragma unroll
            for (int c = 0; c < 4; c++) acc[mi][nj][c] = 0.f;

    #pragma unroll 2
    for (int kc = 0; kc < 16; kc++) {
        uint32_t af[2][4], bf[4][4];
        #pragma unroll
        for (int mi = 0; mi < 2; mi++) {
            uint32_t chunk = kc*2 + aChunkSel;
            uint32_t addr = aBase + (aRow[mi] ^ (chunk << 4));
            LDMX4(af[mi][0], af[mi][1], af[mi][2], af[mi][3], addr);
        }
        #pragma unroll
        for (int njp = 0; njp < 4; njp++) {
            uint32_t chunk = kc*2 + bChunkSel;
            uint32_t addr = bBase + (bRow[njp] ^ (chunk << 4));
            LDMX4(bf[njp][0], bf[njp][1], bf[njp][2], bf[njp][3], addr);
        }
        #pragma unroll
        for (int mi = 0; mi < 2; mi++)
            #pragma unroll
            for (int njp = 0; njp < 4; njp++) {
                MMA16816(acc[mi][njp*2],   af[mi][0], af[mi][1], af[mi][2], af[mi][3],
                         bf[njp][0], bf[njp][1]);
                MMA16816(acc[mi][njp*2+1], af[mi][0], af[mi][1], af[mi][2], af[mi][3],
                         bf[njp][2], bf[njp][3]);
            }
    }
}

// ---------------------------------------------------------------------------
__global__ void k_setup(const float* __restrict__ rel_graph,
                        const float* __restrict__ gumbel,
                        const float* __restrict__ inputs,
                        float* __restrict__ out)
{
    int i = blockIdx.x * blockDim.x + threadIdx.x;
    int stride = gridDim.x * blockDim.x;
    if (i < Ec) {
        float l0 = (rel_graph[2*i]   + gumbel[2*i])   * 2.0f;
        float l1 = (rel_graph[2*i+1] + gumbel[2*i+1]) * 2.0f;
        float m  = fmaxf(l0, l1);
        float e0 = expf(l0 - m), e1 = expf(l1 - m);
        float inv = 1.0f / (e0 + e1);
        g_edges[2*i]   = e0 * inv;
        g_edges[2*i+1] = e1 * inv;
    }
    for (int j = i; j < Bc*Ec*Kc; j += stride)
        out[OFF_REL + j] = rel_graph[j % (Ec*Kc)];
    for (int j = i; j < BTc*Nc*Dc; j += stride) {
        int d  = j & 3;
        int n  = (j >> 2) & 31;
        int bt = j >> 7;
        int b  = bt >> 3, tg = bt & 7;
        g_last[j] = inputs[((b*Nc + n)*Tc + tg*Pc)*Dc + d];
    }
}

// ---------------------------------------------------------------------------
// Prep: W2^T -> fp16, [expert][n][k] rows XOR-swizzled (for ldmatrix B frags)
// ---------------------------------------------------------------------------
__global__ void k_prep(const float* __restrict__ W2)
{
    int g = blockIdx.x * blockDim.x + threadIdx.x;   // 0..16383
    if (g >= 16384) return;
    int ex  = g >> 13;
    int rem = g & 8191;
    int n   = rem >> 5;         // 0..255
    int kg  = (rem & 31) * 8;   // 0..248
    float w[8];
    #pragma unroll
    for (int j = 0; j < 8; j++) w[j] = W2[ex*65536 + (kg + j)*256 + n];
    uint4 pk;
    __half2 h0 = __floats2half2_rn(w[0], w[1]);
    __half2 h1 = __floats2half2_rn(w[2], w[3]);
    __half2 h2 = __floats2half2_rn(w[4], w[5]);
    __half2 h3 = __floats2half2_rn(w[6], w[7]);
    pk.x = *(uint32_t*)&h0; pk.y = *(uint32_t*)&h1;
    pk.z = *(uint32_t*)&h2; pk.w = *(uint32_t*)&h3;
    *(uint4*)((char*)g_W2h + ex*131072 + sw_off(n, kg >> 3)) = pk;
}

// ---------------------------------------------------------------------------
__global__ void k_premsg()
{
    int row = blockIdx.x * blockDim.x + threadIdx.x;
    if (row < ROWS_E) {
        int e  = row % Ec;
        int bt = row / Ec;
        int r  = e / (Nc-1);
        int j  = e % (Nc-1);
        int s  = j + (j >= r);
        float4 a = *(const float4*)(g_last + (bt*Nc + s)*Dc);
        float4 b = *(const float4*)(g_last + (bt*Nc + r)*Dc);
        float4* o = (float4*)(g_premsg + (size_t)row*8);
        o[0] = a; o[1] = b;
    }
    int stride = gridDim.x * blockDim.x;
    for (int j = row; j < BTc*Nc*Hc; j += stride) g_agg[j] = 0.f;
}

// ---------------------------------------------------------------------------
// Edge MLP via mma.sync fp16 tensor cores.
// ---------------------------------------------------------------------------
__global__ void __launch_bounds__(256) k_edge(
    const float* __restrict__ W1, const float* __restrict__ b1,
    const float* __restrict__ b2, float* __restrict__ out, int step)
{
    extern __shared__ __align__(1024) char sm[];
    uint32_t sb = smem_u32(sm);
    int tid = threadIdx.x, wid = tid >> 5, lane = tid & 31;
    int mbase = blockIdx.x * 128;

    // ---- stage loads ----
    {
        int rr = tid >> 1, h = tid & 1;
        *(float4*)(sm + SMEM_PS + (rr*8 + h*4)*4) =
            *(const float4*)(g_premsg + (size_t)(mbase + rr)*8 + h*4);
    }
    {
        const float4* w1p = (const float4*)W1;
        float4* dst = (float4*)(sm + SMEM_W1);
        #pragma unroll
        for (int i = 0; i < 4; i++) dst[tid + i*256] = w1p[tid + i*256];
    }
    {
        float* d1 = (float*)(sm + SMEM_B1);
        float* d2 = (float*)(sm + SMEM_B2);
        d1[tid] = b1[tid]; d1[tid+256] = b1[tid+256];
        d2[tid] = b2[tid]; d2[tid+256] = b2[tid+256];
    }
    if (tid < 128) {
        int grow = mbase + tid;
        int e = grow % Ec, bt = grow / Ec;
        ((float*)(sm + SMEM_EV))[2*tid]   = g_edges[2*e];
        ((float*)(sm + SMEM_EV))[2*tid+1] = g_edges[2*e+1];
        ((int*)(sm + SMEM_GID))[tid]  = bt*Nc + e/(Nc-1);
        ((int*)(sm + SMEM_GEND))[tid] = (e % (Nc-1) == (Nc-2)) ? 1 : 0;
    }
    __syncthreads();

    // ---- A build: both experts, relu(premsg @ W1_e + b1_e) -> fp16 swizzled ----
    {
        int m  = tid >> 1;
        int kh = (tid & 1) * 128;
        float p[8];
        const float* Pr = (const float*)(sm + SMEM_PS) + m*8;
        #pragma unroll
        for (int d = 0; d < 8; d++) p[d] = Pr[d];
        #pragma unroll
        for (int e = 0; e < Kc; e++) {
            const float* W1k = (const float*)(sm + SMEM_W1) + e*2048;
            const float* b1k = (const float*)(sm + SMEM_B1) + e*256;
            #pragma unroll 4
            for (int kg = 0; kg < 16; kg++) {
                int k0 = kh + kg*8;
                float v[8];
                #pragma unroll
                for (int j = 0; j < 8; j++) v[j] = b1k[k0 + j];
                #pragma unroll
                for (int d = 0; d < 8; d++) {
                    const float* wr = W1k + d*256 + k0;
                    #pragma unroll
                    for (int j = 0; j < 8; j++) v[j] += p[d] * wr[j];
                }
                uint4 pk;
                __half2 h0 = __floats2half2_rn(fmaxf(v[0],0.f), fmaxf(v[1],0.f));
                __half2 h1 = __floats2half2_rn(fmaxf(v[2],0.f), fmaxf(v[3],0.f));
                __half2 h2 = __floats2half2_rn(fmaxf(v[4],0.f), fmaxf(v[5],0.f));
                __half2 h3 = __floats2half2_rn(fmaxf(v[6],0.f), fmaxf(v[7],0.f));
                pk.x = *(uint32_t*)&h0; pk.y = *(uint32_t*)&h1;
                pk.z = *(uint32_t*)&h2; pk.w = *(uint32_t*)&h3;
                *(uint4*)(sm + SMEM_A + e*65536 + sw_off(m, k0 >> 3)) = pk;
            }
        }
    }

    // warp tiling: 4 row-warps x 2 col-warps over (m128, n128-half)
    int m0w = (wid & 3) * 32;
    int n0w = (wid >> 2) * 64;
    int lane4 = lane & 3, lrow = lane >> 2;

    // per-row epilogue constants
    float e0v[4], e1v[4]; size_t hookbase[4]; int rowlut[4];
    #pragma unroll
    for (int q = 0; q < 4; q++) {
        int mi = q >> 1, rg = q & 1;
        int row = m0w + mi*16 + rg*8 + lrow;
        rowlut[q] = row;
        e0v[q] = ((const float*)(sm + SMEM_EV))[2*row];
        e1v[q] = ((const float*)(sm + SMEM_EV))[2*row + 1];
        int grow = mbase + row;
        int eG = grow % Ec, btG = grow / Ec;
        int bb = btG >> 3, tg = btG & 7;
        hookbase[q] = (size_t)(((step*TGc + tg)*Bc + bb)*Ec + eG) * Hc;
    }

    // precompute ldmatrix row components
    uint32_t aRow[2], bRow[4];
    #pragma unroll
    for (int mi = 0; mi < 2; mi++) {
        int row = m0w + mi*16 + (lane & 15);
        aRow[mi] = row*512 + ((row & 7) << 4);
    }
    #pragma unroll
    for (int njp = 0; njp < 4; njp++) {
        int row = n0w + njp*16 + ((lane >> 4) << 3) + (lane & 7);
        bRow[njp] = row*512 + ((row & 7) << 4);
    }
    uint32_t aChunkSel = (lane >> 4);
    uint32_t bChunkSel = ((lane >> 3) & 1);

    const float* b2s = (const float*)(sm + SMEM_B2);
    const int* gid  = (const int*)(sm + SMEM_GID);
    const int* gend = (const int*)(sm + SMEM_GEND);

    for (int nhalf = 0; nhalf < 2; nhalf++) {
        // ===== expert 0 =====
        {
            uint4* Bd = (uint4*)(sm + SMEM_B);
            const uint4* src = g_W2h + 0*8192 + nhalf*4096;
            #pragma unroll
            for (int i = 0; i < 16; i++) Bd[tid + i*256] = src[tid + i*256];
        }
        __syncthreads();
        float acc0[2][8][4];
        gemm_pass(acc0, sb + SMEM_A + 0*65536, sb + SMEM_B, aRow, bRow, aChunkSel, bChunkSel);
        __syncthreads();   // all warps done reading B0

        // fold expert-0 epilogue in registers: acc0 <- relu(acc0+b2_0)*e0
        #pragma unroll
        for (int mi = 0; mi < 2; mi++)
            #pragma unroll
            for (int nj = 0; nj < 8; nj++) {
                int colg = nhalf*128 + n0w + nj*8 + lane4*2;
                float ba = b2s[colg], bbv = b2s[colg + 1];
                #pragma unroll
                for (int rg = 0; rg < 2; rg++) {
                    int q = mi*2 + rg;
                    acc0[mi][nj][rg*2]   = fmaxf(acc0[mi][nj][rg*2]   + ba,  0.f) * e0v[q];
                    acc0[mi][nj][rg*2+1] = fmaxf(acc0[mi][nj][rg*2+1] + bbv, 0.f) * e0v[q];
                }
            }

        // ===== expert 1 =====
        {
            uint4* Bd = (uint4*)(sm + SMEM_B);
            const uint4* src = g_W2h + 1*8192 + nhalf*4096;
            #pragma unroll
            for (int i = 0; i < 16; i++) Bd[tid + i*256] = src[tid + i*256];
        }
        __syncthreads();
        float acc1[2][8][4];
        gemm_pass(acc1, sb + SMEM_A + 1*65536, sb + SMEM_B, aRow, bRow, aChunkSel, bChunkSel);
        __syncthreads();   // all warps done reading B1 (Ms reuses this smem)

        // ---- epilogue: expert1 relu/scale, hooks, msv -> Ms smem ----
        #pragma unroll
        for (int mi = 0; mi < 2; mi++)
            #pragma unroll
            for (int nj = 0; nj < 8; nj++) {
                int colh = n0w + nj*8 + lane4*2;
                int colg = nhalf*128 + colh;
                float ba = b2s[256 + colg], bbv = b2s[256 + colg + 1];
                #pragma unroll
                for (int rg = 0; rg < 2; rg++) {
                    int q = mi*2 + rg;
                    float h0 = fmaxf(acc1[mi][nj][rg*2]   + ba,  0.f) * e1v[q];
                    float h1 = fmaxf(acc1[mi][nj][rg*2+1] + bbv, 0.f) * e1v[q];
                    float m0 = acc0[mi][nj][rg*2]   + h0;
                    float m1 = acc0[mi][nj][rg*2+1] + h1;
                    *(float2*)(out + OFF_HOOK + hookbase[q] + colg) = make_float2(h0, h1);
                    *(float2*)(sm + SMEM_B + rowlut[q]*512 + colh*4) = make_float2(m0, m1);
                }
            }
        __syncthreads();

        // ---- segmented reduction over recv-node groups -> g_agg atomics ----
        {
            int col = tid & 127;
            int rh  = tid >> 7;
            int rbeg = rh * 64, rend = rbeg + 64;
            const float* Msf = (const float*)(sm + SMEM_B);
            float accv = 0.f;
            for (int r = rbeg; r < rend; r++) {
                accv += Msf[r*128 + col];
                if (gend[r]) {
                    atomicAdd(g_agg + (size_t)gid[r]*Hc + nhalf*128 + col, accv);
                    accv = 0.f;
                }
            }
            if (!gend[rend-1])
                atomicAdd(g_agg + (size_t)gid[rend-1]*Hc + nhalf*128 + col, accv);
        }
        __syncthreads();
    }
}

// ---------------------------------------------------------------------------
// Node MLP
// ---------------------------------------------------------------------------
__global__ void __launch_bounds__(256) k_node(
    const float* __restrict__ Wo1, const float* __restrict__ bo1,
    const float* __restrict__ Wo2, const float* __restrict__ bo2,
    const float* __restrict__ Wo3, const float* __restrict__ bo3,
    float* __restrict__ out, int step)
{
    __shared__ float augS[16][264];
    __shared__ float h1S[16][264];
    __shared__ float lastS[16][4];
    __shared__ float wo3S[Hc*Dc];

    int tid = threadIdx.x;
    int bt  = blockIdx.x >> 1;
    int nh  = blockIdx.x & 1;
    int n0  = nh * 16;

    for (int i = tid; i < Hc*Dc; i += 256) wo3S[i] = Wo3[i];
    if (tid < 64) {
        int n = tid >> 2, d = tid & 3;
        float v = g_last[(bt*Nc + n0 + n)*Dc + d];
        lastS[n][d] = v;
        augS[n][d]  = v;
    }
    {
        int h = tid;
        #pragma unroll 4
        for (int n = 0; n < 16; n++)
            augS[n][4 + h] = g_agg[((size_t)(bt*Nc + n0 + n))*Hc + h];
    }
    __syncthreads();

    int ty = tid >> 5;
    int tx = tid & 31;
    int r0 = ty*2, r1 = r0 + 1;

    // Layer 1
    {
        float acc0[8], acc1[8];
        #pragma unroll
        for (int c = 0; c < 8; c++) { acc0[c] = 0.f; acc1[c] = 0.f; }
        #pragma unroll 4
        for (int j = 0; j < Dc + Hc; j++) {
            float a0 = augS[r0][j];
            float a1 = augS[r1][j];
            const float4* wp = (const float4*)(Wo1 + j*Hc + tx*8);
            float w[8];
            *(float4*)(w)   = wp[0];
            *(float4*)(w+4) = wp[1];
            #pragma unroll
            for (int c = 0; c < 8; c++) { acc0[c] += a0*w[c]; acc1[c] += a1*w[c]; }
        }
        #pragma unroll
        for (int c = 0; c < 8; c++) {
            float bb = bo1[tx*8 + c];
            h1S[r0][tx*8 + c] = fmaxf(acc0[c] + bb, 0.f);
            h1S[r1][tx*8 + c] = fmaxf(acc1[c] + bb, 0.f);
        }
    }
    __syncthreads();

    // Layer 2
    {
        float acc0[8], acc1[8];
        #pragma unroll
        for (int c = 0; c < 8; c++) { acc0[c] = 0.f; acc1[c] = 0.f; }
        #pragma unroll 4
        for (int j = 0; j < Hc; j++) {
            float a0 = h1S[r0][j];
            float a1 = h1S[r1][j];
            const float4* wp = (const float4*)(Wo2 + j*Hc + tx*8);
            float w[8];
            *(float4*)(w)   = wp[0];
            *(float4*)(w+4) = wp[1];
            #pragma unroll
            for (int c = 0; c < 8; c++) { acc0[c] += a0*w[c]; acc1[c] += a1*w[c]; }
        }
        #pragma unroll
        for (int c = 0; c < 8; c++) {
            float bb = bo2[tx*8 + c];
            augS[r0][4 + tx*8 + c] = fmaxf(acc0[c] + bb, 0.f);
            augS[r1][4 + tx*8 + c] = fmaxf(acc1[c] + bb, 0.f);
        }
    }
    __syncthreads();

    // Layer 3 + residual + writes
    if (tid < 64) {
        int n = tid >> 2, d = tid & 3;
        float v = bo3[d];
        #pragma unroll 8
        for (int c = 0; c < Hc; c++) v += augS[n][4 + c] * wo3S[c*Dc + d];
        float nl = lastS[n][d] + v;
        int gn = n0 + n;
        g_last[(bt*Nc + gn)*Dc + d] = nl;
        int b = bt >> 3, tg = bt & 7;
        int t = tg*Pc + step;
        if (t < Tc - 1)
            out[((b*Nc + gn)*(Tc-1) + t)*Dc + d] = nl;
    }
}

// ---------------------------------------------------------------------------
extern "C" void kernel_launch(void* const* d_in, const int* in_sizes, int n_in,
                              void* d_out, int out_size)
{
    const float* inputs    = (const float*)d_in[0];
    const float* rel_graph = (const float*)d_in[1];
    const float* W1  = (const float*)d_in[2];
    const float* b1  = (const float*)d_in[3];
    const float* W2  = (const float*)d_in[4];
    const float* b2  = (const float*)d_in[5];
    const float* Wo1 = (const float*)d_in[6];
    const float* bo1 = (const float*)d_in[7];
    const float* Wo2 = (const float*)d_in[8];
    const float* bo2 = (const float*)d_in[9];
    const float* Wo3 = (const float*)d_in[10];
    const float* bo3 = (const float*)d_in[11];
    const float* gumbel = (const float*)d_in[14];
    float* out = (float*)d_out;

    cudaFuncSetAttribute(k_edge, cudaFuncAttributeMaxDynamicSharedMemorySize, SMEM_TOTAL);

    k_setup<<<64, 256>>>(rel_graph, gumbel, inputs, out);
    k_prep<<<64, 256>>>(W2);
    for (int p = 0; p < Pc; p++) {
        k_premsg<<<(ROWS_E + 255)/256, 256>>>();
        k_edge<<<ROWS_E/128, 256, SMEM_TOTAL>>>(W1, b1, b2, out, p);
        k_node<<<128, 256>>>(Wo1, bo1, Wo2, bo2, Wo3, bo3, out, p);
    }
}

// round 6
// speedup vs baseline: 3.5943x; 1.3295x over previous
#include <cuda_runtime.h>
#include <cuda_fp16.h>
#include <stdint.h>
#include <math.h>

// Problem constants
#define Bc 8
#define Nc 32
#define Tc 32
#define Dc 4
#define Kc 2
#define Hc 256
#define Pc 4
#define Ec 992            // N*(N-1) = 32*31
#define TGc 8             // T/P
#define BTc 64            // B*TG
#define ROWS_E (BTc*Ec)   // 63488 = 2048*31

// Output layout (float32)
#define SZ_PRED (Bc*Nc*(Tc-1)*Dc)
#define OFF_REL SZ_PRED
#define SZ_REL (Bc*Ec*Kc)
#define OFF_HOOK (OFF_REL + SZ_REL)

// Device scratch (no allocation; BSS zero-initialized)
__device__ float g_edges[Ec*Kc];
__device__ float g_last[BTc*Nc*Dc];
__device__ float g_agg[2048*Hc];        // 2 MB; invariant: zero at kernel_launch entry
__device__ uint4 g_W2h[16384];          // W2^T fp16 [e][n][k] swizzled 512B rows (256 KB)
__device__ uint4 g_W1h[512];            // W1^T fp16 [e][n][d] 16B rows (8 KB)

// ---------------------------------------------------------------------------
// smem layout for k_edge
#define SM_A    0            // A fp16 both experts: 2 x 128 x 512B = 131072
#define SM_B    131072       // B fp16 n-half: 128 x 512B = 65536
#define SM_W1H  196608       // W1h fp16: 8192
#define SM_PMH  204800       // premsg fp16 128 x 16B = 2048
#define SM_B1   206848       // b1 fp32 both: 2048
#define SM_B2   208896       // b2 fp32 both: 2048
#define SMEM_TOTAL 210944

static __device__ __forceinline__ uint32_t smem_u32(const void* p) {
    uint32_t a;
    asm("{ .reg .u64 t; cvta.to.shared.u64 t, %1; cvt.u32.u64 %0, t; }" : "=r"(a) : "l"(p));
    return a;
}
#define LDMX4(r0,r1,r2,r3,addr) \
    asm volatile("ldmatrix.sync.aligned.m8n8.x4.shared.b16 {%0,%1,%2,%3}, [%4];" \
        : "=r"(r0), "=r"(r1), "=r"(r2), "=r"(r3) : "r"(addr))
#define LDMX2(r0,r1,addr) \
    asm volatile("ldmatrix.sync.aligned.m8n8.x2.shared.b16 {%0,%1}, [%2];" \
        : "=r"(r0), "=r"(r1) : "r"(addr))
#define MMA16816(c,a0,a1,a2,a3,b0,b1) \
    asm volatile("mma.sync.aligned.m16n8k16.row.col.f32.f16.f16.f32 " \
        "{%0,%1,%2,%3}, {%4,%5,%6,%7}, {%8,%9}, {%0,%1,%2,%3};" \
        : "+f"((c)[0]), "+f"((c)[1]), "+f"((c)[2]), "+f"((c)[3]) \
        : "r"(a0), "r"(a1), "r"(a2), "r"(a3), "r"(b0), "r"(b1))
#define MMA16808(c,a0,a1,b0) \
    asm volatile("mma.sync.aligned.m16n8k8.row.col.f32.f16.f16.f32 " \
        "{%0,%1,%2,%3}, {%4,%5}, {%6}, {%0,%1,%2,%3};" \
        : "+f"((c)[0]), "+f"((c)[1]), "+f"((c)[2]), "+f"((c)[3]) \
        : "r"(a0), "r"(a1), "r"(b0))
#define CP16(dst, src) \
    asm volatile("cp.async.cg.shared.global [%0], [%1], 16;" :: "r"(dst), "l"(src) : "memory")
#define CP_COMMIT() asm volatile("cp.async.commit_group;" ::: "memory")
#define CP_WAIT(n)  asm volatile("cp.async.wait_group %0;" :: "n"(n) : "memory")

// byte offset of (row, col-in-halves) in a 512B-row swizzled tile
static __device__ __forceinline__ int swb(int r, int c) {
    return r*512 + (((c >> 3) ^ (r & 7)) << 4) + (c & 7)*2;
}
static __device__ __forceinline__ int sw_off(int row, int kchunk) {
    return row*512 + ((kchunk ^ (row & 7)) << 4);
}

// GEMM pass: m32n64 per warp over M128 x N128(half) x K256
static __device__ __forceinline__ void gemm_pass(
    float (&acc)[2][8][4],
    uint32_t aBase, uint32_t bBase,
    const uint32_t (&aRow)[2], const uint32_t (&bRow)[4],
    uint32_t aSel, uint32_t bSel)
{
    #pragma unroll
    for (int mi = 0; mi < 2; mi++)
        #pragma unroll
        for (int nj = 0; nj < 8; nj++)
            #pragma unroll
            for (int c = 0; c < 4; c++) acc[mi][nj][c] = 0.f;

    #pragma unroll 4
    for (int kc = 0; kc < 16; kc++) {
        uint32_t af[2][4], bf[4][4];
        #pragma unroll
        for (int mi = 0; mi < 2; mi++) {
            uint32_t chunk = kc*2 + aSel;
            LDMX4(af[mi][0], af[mi][1], af[mi][2], af[mi][3],
                  aBase + (aRow[mi] ^ (chunk << 4)));
        }
        #pragma unroll
        for (int njp = 0; njp < 4; njp++) {
            uint32_t chunk = kc*2 + bSel;
            LDMX4(bf[njp][0], bf[njp][1], bf[njp][2], bf[njp][3],
                  bBase + (bRow[njp] ^ (chunk << 4)));
        }
        #pragma unroll
        for (int mi = 0; mi < 2; mi++)
            #pragma unroll
            for (int njp = 0; njp < 4; njp++) {
                MMA16816(acc[mi][njp*2],   af[mi][0], af[mi][1], af[mi][2], af[mi][3],
                         bf[njp][0], bf[njp][1]);
                MMA16816(acc[mi][njp*2+1], af[mi][0], af[mi][1], af[mi][2], af[mi][3],
                         bf[njp][2], bf[njp][3]);
            }
    }
}

// ---------------------------------------------------------------------------
__global__ void k_setup(const float* __restrict__ rel_graph,
                        const float* __restrict__ gumbel,
                        const float* __restrict__ inputs,
                        float* __restrict__ out)
{
    int i = blockIdx.x * blockDim.x + threadIdx.x;
    int stride = gridDim.x * blockDim.x;
    if (i < Ec) {
        float l0 = (rel_graph[2*i]   + gumbel[2*i])   * 2.0f;
        float l1 = (rel_graph[2*i+1] + gumbel[2*i+1]) * 2.0f;
        float m  = fmaxf(l0, l1);
        float e0 = expf(l0 - m), e1 = expf(l1 - m);
        float inv = 1.0f / (e0 + e1);
        g_edges[2*i]   = e0 * inv;
        g_edges[2*i+1] = e1 * inv;
    }
    for (int j = i; j < Bc*Ec*Kc; j += stride)
        out[OFF_REL + j] = rel_graph[j % (Ec*Kc)];
    for (int j = i; j < BTc*Nc*Dc; j += stride) {
        int d  = j & 3;
        int n  = (j >> 2) & 31;
        int bt = j >> 7;
        int b  = bt >> 3, tg = bt & 7;
        g_last[j] = inputs[((b*Nc + n)*Tc + tg*Pc)*Dc + d];
    }
    // safety: g_agg zero (also maintained by k_node)
    for (int j = i; j < 2048*Hc; j += stride) g_agg[j] = 0.f;
}

// ---------------------------------------------------------------------------
// Prep: W2^T fp16 swizzled rows; W1^T fp16 [e][n][d]
// ---------------------------------------------------------------------------
__global__ void k_prep(const float* __restrict__ W2, const float* __restrict__ W1)
{
    int g = blockIdx.x * blockDim.x + threadIdx.x;
    if (g < 16384) {
        int ex  = g >> 13;
        int rem = g & 8191;
        int n   = rem >> 5;
        int kg  = (rem & 31) * 8;
        float w[8];
        #pragma unroll
        for (int j = 0; j < 8; j++) w[j] = W2[ex*65536 + (kg + j)*256 + n];
        uint4 pk;
        __half2 h0 = __floats2half2_rn(w[0], w[1]);
        __half2 h1 = __floats2half2_rn(w[2], w[3]);
        __half2 h2 = __floats2half2_rn(w[4], w[5]);
        __half2 h3 = __floats2half2_rn(w[6], w[7]);
        pk.x = *(uint32_t*)&h0; pk.y = *(uint32_t*)&h1;
        pk.z = *(uint32_t*)&h2; pk.w = *(uint32_t*)&h3;
        *(uint4*)((char*)g_W2h + ex*131072 + sw_off(n, kg >> 3)) = pk;
    }
    if (g < 512) {
        int ex = g >> 8, n = g & 255;
        float w[8];
        #pragma unroll
        for (int d = 0; d < 8; d++) w[d] = W1[ex*2048 + d*256 + n];
        uint4 pk;
        __half2 h0 = __floats2half2_rn(w[0], w[1]);
        __half2 h1 = __floats2half2_rn(w[2], w[3]);
        __half2 h2 = __floats2half2_rn(w[4], w[5]);
        __half2 h3 = __floats2half2_rn(w[6], w[7]);
        pk.x = *(uint32_t*)&h0; pk.y = *(uint32_t*)&h1;
        pk.z = *(uint32_t*)&h2; pk.w = *(uint32_t*)&h3;
        g_W1h[g] = pk;
    }
}

// ---------------------------------------------------------------------------
// Edge MLP: mma A-build + cp.async-pipelined HMMA GEMM + fused epilogue
// ---------------------------------------------------------------------------
__global__ void __launch_bounds__(256) k_edge(
    const float* __restrict__ b1, const float* __restrict__ b2,
    float* __restrict__ out, int step)
{
    extern __shared__ __align__(1024) char sm[];
    uint32_t sb = smem_u32(sm);
    int tid = threadIdx.x, wid = tid >> 5, lane = tid & 31;
    int mbase = blockIdx.x * 128;

    // ---- async staged loads: W1h (group 0), B(e0,h0) (group 1) ----
    CP16(sb + SM_W1H + tid*16, (const void*)(g_W1h + tid));
    CP16(sb + SM_W1H + 4096 + tid*16, (const void*)(g_W1h + 256 + tid));
    CP_COMMIT();
    {
        const uint4* src = g_W2h;   // e=0, h=0
        uint32_t dst = sb + SM_B + tid*16;
        #pragma unroll
        for (int i = 0; i < 16; i++) CP16(dst + i*4096, (const void*)(src + tid + i*256));
    }
    CP_COMMIT();

    // biases
    {
        float* d1 = (float*)(sm + SM_B1);
        float* d2 = (float*)(sm + SM_B2);
        d1[tid] = b1[tid]; d1[tid+256] = b1[tid+256];
        d2[tid] = b2[tid]; d2[tid+256] = b2[tid+256];
    }
    // premsg gather -> fp16 smem rows
    if (tid < 128) {
        int grow = mbase + tid;
        int bt = grow / Ec, e = grow - bt*Ec;
        int r  = e / (Nc-1), j = e - r*(Nc-1);
        int s  = j + (j >= r);
        float4 a = *(const float4*)(g_last + (bt*Nc + s)*Dc);
        float4 b = *(const float4*)(g_last + (bt*Nc + r)*Dc);
        uint4 pk;
        __half2 h0 = __floats2half2_rn(a.x, a.y);
        __half2 h1 = __floats2half2_rn(a.z, a.w);
        __half2 h2 = __floats2half2_rn(b.x, b.y);
        __half2 h3 = __floats2half2_rn(b.z, b.w);
        pk.x = *(uint32_t*)&h0; pk.y = *(uint32_t*)&h1;
        pk.z = *(uint32_t*)&h2; pk.w = *(uint32_t*)&h3;
        *(uint4*)(sm + SM_PMH + tid*16) = pk;
    }

    CP_WAIT(1);          // W1h ready (B may still be in flight)
    __syncthreads();

    // ---- A build via mma.m16n8k8: A[e][m][k] = relu(premsg @ W1_e + b1_e) ----
    {
        int m0 = wid * 16;
        uint32_t a0, a1;
        LDMX2(a0, a1, sb + SM_PMH + (m0 + (lane & 15))*16);
        #pragma unroll
        for (int e = 0; e < 2; e++) {
            const float* b1e = (const float*)(sm + SM_B1) + e*256;
            #pragma unroll
            for (int nc = 0; nc < 8; nc++) {
                uint32_t bf[4];
                LDMX4(bf[0], bf[1], bf[2], bf[3],
                      sb + SM_W1H + e*4096 + (nc*32 + lane)*16);
                #pragma unroll
                for (int c = 0; c < 4; c++) {
                    float acc[4] = {0.f, 0.f, 0.f, 0.f};
                    MMA16808(acc, a0, a1, bf[c]);
                    int col = nc*32 + c*8 + (lane & 3)*2;
                    float bx = b1e[col], by = b1e[col+1];
                    __half2 v0 = __floats2half2_rn(fmaxf(acc[0]+bx, 0.f), fmaxf(acc[1]+by, 0.f));
                    __half2 v1 = __floats2half2_rn(fmaxf(acc[2]+bx, 0.f), fmaxf(acc[3]+by, 0.f));
                    int r0 = m0 + (lane >> 2), r1 = r0 + 8;
                    *(__half2*)(sm + SM_A + e*65536 + swb(r0, col)) = v0;
                    *(__half2*)(sm + SM_A + e*65536 + swb(r1, col)) = v1;
                }
            }
        }
    }
    CP_WAIT(0);
    __syncthreads();     // A + B(e0,h0) ready

    // ---- warp tiling: 4 m-warps (m32) x 2 n-warps (n64) ----
    int wm = wid & 3, wn = wid >> 2;
    int lrow = lane >> 2, lane4 = lane & 3;

    uint32_t aRow[2], bRow[4];
    #pragma unroll
    for (int mi = 0; mi < 2; mi++) {
        int row = wm*32 + mi*16 + (lane & 15);
        aRow[mi] = row*512 + ((row & 7) << 4);
    }
    #pragma unroll
    for (int njp = 0; njp < 4; njp++) {
        int row = wn*64 + njp*16 + ((lane >> 4) << 3) + (lane & 7);
        bRow[njp] = row*512 + ((row & 7) << 4);
    }
    uint32_t aSel = lane >> 4, bSel = (lane >> 3) & 1;

    // per-row epilogue constants
    float e0v[4], e1v[4]; size_t hookbase[4];
    #pragma unroll
    for (int q = 0; q < 4; q++) {
        int mi = q >> 1, rg = q & 1;
        int grow = mbase + wm*32 + mi*16 + rg*8 + lrow;
        int bt = grow / Ec, eG = grow - bt*Ec;
        e0v[q] = g_edges[2*eG];
        e1v[q] = g_edges[2*eG+1];
        int bb = bt >> 3, tg = bt & 7;
        hookbase[q] = (size_t)(((step*TGc + tg)*Bc + bb)*Ec + eG) * Hc;
    }
    // segmented-reduction constants (group len 31; <=1 boundary per 32-row strip)
    int gs   = mbase + wm*32;
    int G0   = gs / 31;
    int bnd  = 31 - (gs - G0*31);

    const float* b2s = (const float*)(sm + SM_B2);

    for (int h = 0; h < 2; h++) {
        // ===== expert 0 (B holds e0,h) =====
        float acc0[2][8][4];
        gemm_pass(acc0, sb + SM_A, sb + SM_B, aRow, bRow, aSel, bSel);
        __syncthreads();
        {   // prefetch B(e1,h)
            const uint4* src = g_W2h + 8192 + h*4096;
            uint32_t dst = sb + SM_B + tid*16;
            #pragma unroll
            for (int i = 0; i < 16; i++) CP16(dst + i*4096, (const void*)(src + tid + i*256));
            CP_COMMIT();
        }
        // fold expert-0 epilogue in regs
        #pragma unroll
        for (int mi = 0; mi < 2; mi++)
            #pragma unroll
            for (int nj = 0; nj < 8; nj++) {
                int cg = h*128 + wn*64 + nj*8 + lane4*2;
                float bx = b2s[cg], by = b2s[cg+1];
                #pragma unroll
                for (int rg = 0; rg < 2; rg++) {
                    int q = mi*2 + rg;
                    acc0[mi][nj][rg*2]   = fmaxf(acc0[mi][nj][rg*2]   + bx, 0.f) * e0v[q];
                    acc0[mi][nj][rg*2+1] = fmaxf(acc0[mi][nj][rg*2+1] + by, 0.f) * e0v[q];
                }
            }
        CP_WAIT(0);
        __syncthreads();

        // ===== expert 1 =====
        float acc1[2][8][4];
        gemm_pass(acc1, sb + SM_A + 65536, sb + SM_B, aRow, bRow, aSel, bSel);
        __syncthreads();
        if (h == 0) {   // prefetch B(e0,1)
            const uint4* src = g_W2h + 4096;
            uint32_t dst = sb + SM_B + tid*16;
            #pragma unroll
            for (int i = 0; i < 16; i++) CP16(dst + i*4096, (const void*)(src + tid + i*256));
            CP_COMMIT();
        }

        // ---- epilogue: combine, hooks, shuffle segmented reduction ----
        #pragma unroll
        for (int nj = 0; nj < 8; nj++) {
            int cl = wn*64 + nj*8 + lane4*2;
            int cg = h*128 + cl;
            float bx = b2s[256 + cg], by = b2s[256 + cg + 1];
            float pA0 = 0.f, pA1 = 0.f, pB0 = 0.f, pB1 = 0.f;
            #pragma unroll
            for (int mi = 0; mi < 2; mi++)
                #pragma unroll
                for (int rg = 0; rg < 2; rg++) {
                    int q = mi*2 + rg;
                    float h0 = fmaxf(acc1[mi][nj][rg*2]   + bx, 0.f) * e1v[q];
                    float h1 = fmaxf(acc1[mi][nj][rg*2+1] + by, 0.f) * e1v[q];
                    float m0 = acc0[mi][nj][rg*2]   + h0;
                    float m1 = acc0[mi][nj][rg*2+1] + h1;
                    *(float2*)(out + OFF_HOOK + hookbase[q] + cg) = make_float2(h0, h1);
                    int rel = mi*16 + rg*8 + lrow;
                    if (rel < bnd) { pA0 += m0; pA1 += m1; }
                    else           { pB0 += m0; pB1 += m1; }
                }
            #pragma unroll
            for (int d = 4; d <= 16; d <<= 1) {
                pA0 += __shfl_xor_sync(0xffffffffu, pA0, d);
                pA1 += __shfl_xor_sync(0xffffffffu, pA1, d);
                pB0 += __shfl_xor_sync(0xffffffffu, pB0, d);
                pB1 += __shfl_xor_sync(0xffffffffu, pB1, d);
            }
            if (lane < 4) {
                atomicAdd(g_agg + (size_t)G0*Hc + cg,           pA0);
                atomicAdd(g_agg + (size_t)G0*Hc + cg + 1,       pA1);
                atomicAdd(g_agg + (size_t)(G0+1)*Hc + cg,       pB0);
                atomicAdd(g_agg + (size_t)(G0+1)*Hc + cg + 1,   pB1);
            }
        }
        if (h == 0) {
            CP_WAIT(0);
            __syncthreads();
        }
    }
}

// ---------------------------------------------------------------------------
// Node MLP: 256 blocks x 8 rows; reads + zeroes g_agg
// ---------------------------------------------------------------------------
__global__ void __launch_bounds__(256) k_node(
    const float* __restrict__ Wo1, const float* __restrict__ bo1,
    const float* __restrict__ Wo2, const float* __restrict__ bo2,
    const float* __restrict__ Wo3, const float* __restrict__ bo3,
    float* __restrict__ out, int step)
{
    __shared__ float augS[8][264];
    __shared__ float h1S[8][264];
    __shared__ float lastS[8][4];
    __shared__ float wo3S[Hc*Dc];

    int tid = threadIdx.x;
    int ty = tid >> 5, lane = tid & 31;
    int base_row = blockIdx.x * 8;

    for (int i = tid; i < Hc*Dc; i += 256) wo3S[i] = Wo3[i];
    if (tid < 32) {
        int n = tid >> 2, d = tid & 3;
        float v = g_last[(base_row + n)*Dc + d];
        lastS[n][d] = v;
        augS[n][d]  = v;
    }
    {   // agg read + zero
        float* src = g_agg + (size_t)(base_row + ty)*Hc + lane*8;
        float4 v0 = *(float4*)src, v1 = *(float4*)(src + 4);
        *(float4*)(&augS[ty][4 + lane*8])     = v0;
        *(float4*)(&augS[ty][4 + lane*8 + 4]) = v1;
        float4 z = make_float4(0.f, 0.f, 0.f, 0.f);
        *(float4*)src = z; *(float4*)(src + 4) = z;
    }
    __syncthreads();

    // Layer 1: row ty, cols lane*8..+7
    {
        float acc[8];
        #pragma unroll
        for (int c = 0; c < 8; c++) acc[c] = 0.f;
        #pragma unroll 4
        for (int j = 0; j < Dc + Hc; j++) {
            float a = augS[ty][j];
            const float4* wp = (const float4*)(Wo1 + j*Hc + lane*8);
            float w[8];
            *(float4*)(w)   = wp[0];
            *(float4*)(w+4) = wp[1];
            #pragma unroll
            for (int c = 0; c < 8; c++) acc[c] += a*w[c];
        }
        #pragma unroll
        for (int c = 0; c < 8; c++)
            h1S[ty][lane*8 + c] = fmaxf(acc[c] + bo1[lane*8 + c], 0.f);
    }
    __syncthreads();

    // Layer 2
    {
        float acc[8];
        #pragma unroll
        for (int c = 0; c < 8; c++) acc[c] = 0.f;
        #pragma unroll 4
        for (int j = 0; j < Hc; j++) {
            float a = h1S[ty][j];
            const float4* wp = (const float4*)(Wo2 + j*Hc + lane*8);
            float w[8];
            *(float4*)(w)   = wp[0];
            *(float4*)(w+4) = wp[1];
            #pragma unroll
            for (int c = 0; c < 8; c++) acc[c] += a*w[c];
        }
        #pragma unroll
        for (int c = 0; c < 8; c++)
            augS[ty][4 + lane*8 + c] = fmaxf(acc[c] + bo2[lane*8 + c], 0.f);
    }
    __syncthreads();

    // Layer 3 + residual + writes
    if (tid < 32) {
        int n = tid >> 2, d = tid & 3;
        float v = bo3[d];
        #pragma unroll 8
        for (int c = 0; c < Hc; c++) v += augS[n][4 + c] * wo3S[c*Dc + d];
        float nl = lastS[n][d] + v;
        int grow = base_row + n;
        g_last[grow*Dc + d] = nl;
        int bt = grow >> 5, gn = grow & 31;
        int b = bt >> 3, tg = bt & 7;
        int t = tg*Pc + step;
        if (t < Tc - 1)
            out[((b*Nc + gn)*(Tc-1) + t)*Dc + d] = nl;
    }
}

// ---------------------------------------------------------------------------
extern "C" void kernel_launch(void* const* d_in, const int* in_sizes, int n_in,
                              void* d_out, int out_size)
{
    const float* inputs    = (const float*)d_in[0];
    const float* rel_graph = (const float*)d_in[1];
    const float* W1  = (const float*)d_in[2];
    const float* b1  = (const float*)d_in[3];
    const float* W2  = (const float*)d_in[4];
    const float* b2  = (const float*)d_in[5];
    const float* Wo1 = (const float*)d_in[6];
    const float* bo1 = (const float*)d_in[7];
    const float* Wo2 = (const float*)d_in[8];
    const float* bo2 = (const float*)d_in[9];
    const float* Wo3 = (const float*)d_in[10];
    const float* bo3 = (const float*)d_in[11];
    const float* gumbel = (const float*)d_in[14];
    float* out = (float*)d_out;

    cudaFuncSetAttribute(k_edge, cudaFuncAttributeMaxDynamicSharedMemorySize, SMEM_TOTAL);

    k_setup<<<64, 256>>>(rel_graph, gumbel, inputs, out);
    k_prep<<<64, 256>>>(W2, W1);
    for (int p = 0; p < Pc; p++) {
        k_edge<<<ROWS_E/128, 256, SMEM_TOTAL>>>(b1, b2, out, p);
        k_node<<<256, 256>>>(Wo1, bo1, Wo2, bo2, Wo3, bo3, out, p);
    }
}

// round 7
// speedup vs baseline: 5.0989x; 1.4186x over previous
#include <cuda_runtime.h>
#include <cuda_fp16.h>
#include <stdint.h>
#include <math.h>

// Problem constants
#define Bc 8
#define Nc 32
#define Tc 32
#define Dc 4
#define Kc 2
#define Hc 256
#define Pc 4
#define Ec 992            // N*(N-1) = 32*31
#define TGc 8             // T/P
#define BTc 64            // B*TG
#define ROWS_E (BTc*Ec)   // 63488 = 2048*31

// Output layout (float32)
#define SZ_PRED (Bc*Nc*(Tc-1)*Dc)
#define OFF_REL SZ_PRED
#define SZ_REL (Bc*Ec*Kc)
#define OFF_HOOK (OFF_REL + SZ_REL)

// Device scratch (no allocation; BSS zero-initialized)
__device__ float g_edges[Ec*Kc];
__device__ float g_last[BTc*Nc*Dc];
__device__ float g_agg[2048*Hc];        // 2 MB; invariant: zero at kernel_launch entry
__device__ uint4 g_W2h[16384];          // W2^T fp16 [e][n][k] swizzled 512B rows (256 KB)
__device__ uint4 g_W1h[512];            // W1^T fp16 [e][n][d] 16B rows (8 KB)

// ---------------------------------------------------------------------------
// smem layout for k_edge
#define SM_A    0            // A fp16 both experts: 2 x 128 x 512B = 131072
#define SM_B    131072       // B fp16 n-half: 128 x 512B = 65536
#define SM_W1H  196608       // W1h fp16: 8192
#define SM_PMH  204800       // premsg fp16 128 x 16B = 2048
#define SM_B1   206848       // b1 fp32 both: 2048
#define SM_B2   208896       // b2 fp32 both: 2048
#define SMEM_TOTAL 210944

static __device__ __forceinline__ uint32_t smem_u32(const void* p) {
    uint32_t a;
    asm("{ .reg .u64 t; cvta.to.shared.u64 t, %1; cvt.u32.u64 %0, t; }" : "=r"(a) : "l"(p));
    return a;
}
#define LDMX4(r0,r1,r2,r3,addr) \
    asm volatile("ldmatrix.sync.aligned.m8n8.x4.shared.b16 {%0,%1,%2,%3}, [%4];" \
        : "=r"(r0), "=r"(r1), "=r"(r2), "=r"(r3) : "r"(addr))
#define LDMX2(r0,r1,addr) \
    asm volatile("ldmatrix.sync.aligned.m8n8.x2.shared.b16 {%0,%1}, [%2];" \
        : "=r"(r0), "=r"(r1) : "r"(addr))
#define MMA16816(c,a0,a1,a2,a3,b0,b1) \
    asm volatile("mma.sync.aligned.m16n8k16.row.col.f32.f16.f16.f32 " \
        "{%0,%1,%2,%3}, {%4,%5,%6,%7}, {%8,%9}, {%0,%1,%2,%3};" \
        : "+f"((c)[0]), "+f"((c)[1]), "+f"((c)[2]), "+f"((c)[3]) \
        : "r"(a0), "r"(a1), "r"(a2), "r"(a3), "r"(b0), "r"(b1))
#define MMA16808(c,a0,a1,b0) \
    asm volatile("mma.sync.aligned.m16n8k8.row.col.f32.f16.f16.f32 " \
        "{%0,%1,%2,%3}, {%4,%5}, {%6}, {%0,%1,%2,%3};" \
        : "+f"((c)[0]), "+f"((c)[1]), "+f"((c)[2]), "+f"((c)[3]) \
        : "r"(a0), "r"(a1), "r"(b0))
#define CP16(dst, src) \
    asm volatile("cp.async.cg.shared.global [%0], [%1], 16;" :: "r"(dst), "l"(src) : "memory")
#define CP_COMMIT() asm volatile("cp.async.commit_group;" ::: "memory")
#define CP_WAIT(n)  asm volatile("cp.async.wait_group %0;" :: "n"(n) : "memory")

static __device__ __forceinline__ int swb(int r, int c) {
    return r*512 + (((c >> 3) ^ (r & 7)) << 4) + (c & 7)*2;
}
static __device__ __forceinline__ int sw_off(int row, int kchunk) {
    return row*512 + ((kchunk ^ (row & 7)) << 4);
}

// GEMM pass: m32n64 per warp over M128 x N128(half) x K256
static __device__ __forceinline__ void gemm_pass(
    float (&acc)[2][8][4],
    uint32_t aBase, uint32_t bBase,
    const uint32_t (&aRow)[2], const uint32_t (&bRow)[4],
    uint32_t aSel, uint32_t bSel)
{
    #pragma unroll
    for (int mi = 0; mi < 2; mi++)
        #pragma unroll
        for (int nj = 0; nj < 8; nj++)
            #pragma unroll
            for (int c = 0; c < 4; c++) acc[mi][nj][c] = 0.f;

    #pragma unroll 4
    for (int kc = 0; kc < 16; kc++) {
        uint32_t af[2][4], bf[4][4];
        #pragma unroll
        for (int mi = 0; mi < 2; mi++) {
            uint32_t chunk = kc*2 + aSel;
            LDMX4(af[mi][0], af[mi][1], af[mi][2], af[mi][3],
                  aBase + (aRow[mi] ^ (chunk << 4)));
        }
        #pragma unroll
        for (int njp = 0; njp < 4; njp++) {
            uint32_t chunk = kc*2 + bSel;
            LDMX4(bf[njp][0], bf[njp][1], bf[njp][2], bf[njp][3],
                  bBase + (bRow[njp] ^ (chunk << 4)));
        }
        #pragma unroll
        for (int mi = 0; mi < 2; mi++)
            #pragma unroll
            for (int njp = 0; njp < 4; njp++) {
                MMA16816(acc[mi][njp*2],   af[mi][0], af[mi][1], af[mi][2], af[mi][3],
                         bf[njp][0], bf[njp][1]);
                MMA16816(acc[mi][njp*2+1], af[mi][0], af[mi][1], af[mi][2], af[mi][3],
                         bf[njp][2], bf[njp][3]);
            }
    }
}

// ---------------------------------------------------------------------------
__global__ void k_setup(const float* __restrict__ rel_graph,
                        const float* __restrict__ gumbel,
                        const float* __restrict__ inputs,
                        float* __restrict__ out)
{
    int i = blockIdx.x * blockDim.x + threadIdx.x;
    int stride = gridDim.x * blockDim.x;
    if (i < Ec) {
        float l0 = (rel_graph[2*i]   + gumbel[2*i])   * 2.0f;
        float l1 = (rel_graph[2*i+1] + gumbel[2*i+1]) * 2.0f;
        float m  = fmaxf(l0, l1);
        float e0 = expf(l0 - m), e1 = expf(l1 - m);
        float inv = 1.0f / (e0 + e1);
        g_edges[2*i]   = e0 * inv;
        g_edges[2*i+1] = e1 * inv;
    }
    for (int j = i; j < Bc*Ec*Kc; j += stride)
        out[OFF_REL + j] = rel_graph[j % (Ec*Kc)];
    for (int j = i; j < BTc*Nc*Dc; j += stride) {
        int d  = j & 3;
        int n  = (j >> 2) & 31;
        int bt = j >> 7;
        int b  = bt >> 3, tg = bt & 7;
        g_last[j] = inputs[((b*Nc + n)*Tc + tg*Pc)*Dc + d];
    }
    for (int j = i; j < 2048*Hc; j += stride) g_agg[j] = 0.f;
}

// ---------------------------------------------------------------------------
__global__ void k_prep(const float* __restrict__ W2, const float* __restrict__ W1)
{
    int g = blockIdx.x * blockDim.x + threadIdx.x;
    if (g < 16384) {
        int ex  = g >> 13;
        int rem = g & 8191;
        int n   = rem >> 5;
        int kg  = (rem & 31) * 8;
        float w[8];
        #pragma unroll
        for (int j = 0; j < 8; j++) w[j] = W2[ex*65536 + (kg + j)*256 + n];
        uint4 pk;
        __half2 h0 = __floats2half2_rn(w[0], w[1]);
        __half2 h1 = __floats2half2_rn(w[2], w[3]);
        __half2 h2 = __floats2half2_rn(w[4], w[5]);
        __half2 h3 = __floats2half2_rn(w[6], w[7]);
        pk.x = *(uint32_t*)&h0; pk.y = *(uint32_t*)&h1;
        pk.z = *(uint32_t*)&h2; pk.w = *(uint32_t*)&h3;
        *(uint4*)((char*)g_W2h + ex*131072 + sw_off(n, kg >> 3)) = pk;
    }
    if (g < 512) {
        int ex = g >> 8, n = g & 255;
        float w[8];
        #pragma unroll
        for (int d = 0; d < 8; d++) w[d] = W1[ex*2048 + d*256 + n];
        uint4 pk;
        __half2 h0 = __floats2half2_rn(w[0], w[1]);
        __half2 h1 = __floats2half2_rn(w[2], w[3]);
        __half2 h2 = __floats2half2_rn(w[4], w[5]);
        __half2 h3 = __floats2half2_rn(w[6], w[7]);
        pk.x = *(uint32_t*)&h0; pk.y = *(uint32_t*)&h1;
        pk.z = *(uint32_t*)&h2; pk.w = *(uint32_t*)&h3;
        g_W1h[g] = pk;
    }
}

// ---------------------------------------------------------------------------
// Edge MLP: mma A-build + cp.async-pipelined HMMA GEMM + fused epilogue
// ---------------------------------------------------------------------------
__global__ void __launch_bounds__(256) k_edge(
    const float* __restrict__ b1, const float* __restrict__ b2,
    float* __restrict__ out, int step)
{
    extern __shared__ __align__(1024) char sm[];
    uint32_t sb = smem_u32(sm);
    int tid = threadIdx.x, wid = tid >> 5, lane = tid & 31;
    int mbase = blockIdx.x * 128;

    CP16(sb + SM_W1H + tid*16, (const void*)(g_W1h + tid));
    CP16(sb + SM_W1H + 4096 + tid*16, (const void*)(g_W1h + 256 + tid));
    CP_COMMIT();
    {
        const uint4* src = g_W2h;   // e=0, h=0
        uint32_t dst = sb + SM_B + tid*16;
        #pragma unroll
        for (int i = 0; i < 16; i++) CP16(dst + i*4096, (const void*)(src + tid + i*256));
    }
    CP_COMMIT();

    {
        float* d1 = (float*)(sm + SM_B1);
        float* d2 = (float*)(sm + SM_B2);
        d1[tid] = b1[tid]; d1[tid+256] = b1[tid+256];
        d2[tid] = b2[tid]; d2[tid+256] = b2[tid+256];
    }
    if (tid < 128) {
        int grow = mbase + tid;
        int bt = grow / Ec, e = grow - bt*Ec;
        int r  = e / (Nc-1), j = e - r*(Nc-1);
        int s  = j + (j >= r);
        float4 a = *(const float4*)(g_last + (bt*Nc + s)*Dc);
        float4 b = *(const float4*)(g_last + (bt*Nc + r)*Dc);
        uint4 pk;
        __half2 h0 = __floats2half2_rn(a.x, a.y);
        __half2 h1 = __floats2half2_rn(a.z, a.w);
        __half2 h2 = __floats2half2_rn(b.x, b.y);
        __half2 h3 = __floats2half2_rn(b.z, b.w);
        pk.x = *(uint32_t*)&h0; pk.y = *(uint32_t*)&h1;
        pk.z = *(uint32_t*)&h2; pk.w = *(uint32_t*)&h3;
        *(uint4*)(sm + SM_PMH + tid*16) = pk;
    }

    CP_WAIT(1);
    __syncthreads();

    // ---- A build via mma.m16n8k8 ----
    {
        int m0 = wid * 16;
        uint32_t a0, a1;
        LDMX2(a0, a1, sb + SM_PMH + (m0 + (lane & 15))*16);
        #pragma unroll
        for (int e = 0; e < 2; e++) {
            const float* b1e = (const float*)(sm + SM_B1) + e*256;
            #pragma unroll
            for (int nc = 0; nc < 8; nc++) {
                uint32_t bf[4];
                LDMX4(bf[0], bf[1], bf[2], bf[3],
                      sb + SM_W1H + e*4096 + (nc*32 + lane)*16);
                #pragma unroll
                for (int c = 0; c < 4; c++) {
                    float acc[4] = {0.f, 0.f, 0.f, 0.f};
                    MMA16808(acc, a0, a1, bf[c]);
                    int col = nc*32 + c*8 + (lane & 3)*2;
                    float bx = b1e[col], by = b1e[col+1];
                    __half2 v0 = __floats2half2_rn(fmaxf(acc[0]+bx, 0.f), fmaxf(acc[1]+by, 0.f));
                    __half2 v1 = __floats2half2_rn(fmaxf(acc[2]+bx, 0.f), fmaxf(acc[3]+by, 0.f));
                    int r0 = m0 + (lane >> 2), r1 = r0 + 8;
                    *(__half2*)(sm + SM_A + e*65536 + swb(r0, col)) = v0;
                    *(__half2*)(sm + SM_A + e*65536 + swb(r1, col)) = v1;
                }
            }
        }
    }
    CP_WAIT(0);
    __syncthreads();

    int wm = wid & 3, wn = wid >> 2;
    int lrow = lane >> 2, lane4 = lane & 3;

    uint32_t aRow[2], bRow[4];
    #pragma unroll
    for (int mi = 0; mi < 2; mi++) {
        int row = wm*32 + mi*16 + (lane & 15);
        aRow[mi] = row*512 + ((row & 7) << 4);
    }
    #pragma unroll
    for (int njp = 0; njp < 4; njp++) {
        int row = wn*64 + njp*16 + ((lane >> 4) << 3) + (lane & 7);
        bRow[njp] = row*512 + ((row & 7) << 4);
    }
    uint32_t aSel = lane >> 4, bSel = (lane >> 3) & 1;

    float e0v[4], e1v[4]; size_t hookbase[4];
    #pragma unroll
    for (int q = 0; q < 4; q++) {
        int mi = q >> 1, rg = q & 1;
        int grow = mbase + wm*32 + mi*16 + rg*8 + lrow;
        int bt = grow / Ec, eG = grow - bt*Ec;
        e0v[q] = g_edges[2*eG];
        e1v[q] = g_edges[2*eG+1];
        int bb = bt >> 3, tg = bt & 7;
        hookbase[q] = (size_t)(((step*TGc + tg)*Bc + bb)*Ec + eG) * Hc;
    }
    int gs   = mbase + wm*32;
    int G0   = gs / 31;
    int bnd  = 31 - (gs - G0*31);

    const float* b2s = (const float*)(sm + SM_B2);

    for (int h = 0; h < 2; h++) {
        float acc0[2][8][4];
        gemm_pass(acc0, sb + SM_A, sb + SM_B, aRow, bRow, aSel, bSel);
        __syncthreads();
        {
            const uint4* src = g_W2h + 8192 + h*4096;
            uint32_t dst = sb + SM_B + tid*16;
            #pragma unroll
            for (int i = 0; i < 16; i++) CP16(dst + i*4096, (const void*)(src + tid + i*256));
            CP_COMMIT();
        }
        #pragma unroll
        for (int mi = 0; mi < 2; mi++)
            #pragma unroll
            for (int nj = 0; nj < 8; nj++) {
                int cg = h*128 + wn*64 + nj*8 + lane4*2;
                float bx = b2s[cg], by = b2s[cg+1];
                #pragma unroll
                for (int rg = 0; rg < 2; rg++) {
                    int q = mi*2 + rg;
                    acc0[mi][nj][rg*2]   = fmaxf(acc0[mi][nj][rg*2]   + bx, 0.f) * e0v[q];
                    acc0[mi][nj][rg*2+1] = fmaxf(acc0[mi][nj][rg*2+1] + by, 0.f) * e0v[q];
                }
            }
        CP_WAIT(0);
        __syncthreads();

        float acc1[2][8][4];
        gemm_pass(acc1, sb + SM_A + 65536, sb + SM_B, aRow, bRow, aSel, bSel);
        __syncthreads();
        if (h == 0) {
            const uint4* src = g_W2h + 4096;
            uint32_t dst = sb + SM_B + tid*16;
            #pragma unroll
            for (int i = 0; i < 16; i++) CP16(dst + i*4096, (const void*)(src + tid + i*256));
            CP_COMMIT();
        }

        #pragma unroll
        for (int nj = 0; nj < 8; nj++) {
            int cl = wn*64 + nj*8 + lane4*2;
            int cg = h*128 + cl;
            float bx = b2s[256 + cg], by = b2s[256 + cg + 1];
            float pA0 = 0.f, pA1 = 0.f, pB0 = 0.f, pB1 = 0.f;
            #pragma unroll
            for (int mi = 0; mi < 2; mi++)
                #pragma unroll
                for (int rg = 0; rg < 2; rg++) {
                    int q = mi*2 + rg;
                    float h0 = fmaxf(acc1[mi][nj][rg*2]   + bx, 0.f) * e1v[q];
                    float h1 = fmaxf(acc1[mi][nj][rg*2+1] + by, 0.f) * e1v[q];
                    float m0 = acc0[mi][nj][rg*2]   + h0;
                    float m1 = acc0[mi][nj][rg*2+1] + h1;
                    *(float2*)(out + OFF_HOOK + hookbase[q] + cg) = make_float2(h0, h1);
                    int rel = mi*16 + rg*8 + lrow;
                    if (rel < bnd) { pA0 += m0; pA1 += m1; }
                    else           { pB0 += m0; pB1 += m1; }
                }
            #pragma unroll
            for (int d = 4; d <= 16; d <<= 1) {
                pA0 += __shfl_xor_sync(0xffffffffu, pA0, d);
                pA1 += __shfl_xor_sync(0xffffffffu, pA1, d);
                pB0 += __shfl_xor_sync(0xffffffffu, pB0, d);
                pB1 += __shfl_xor_sync(0xffffffffu, pB1, d);
            }
            if (lane < 4) {
                atomicAdd(g_agg + (size_t)G0*Hc + cg,           pA0);
                atomicAdd(g_agg + (size_t)G0*Hc + cg + 1,       pA1);
                atomicAdd(g_agg + (size_t)(G0+1)*Hc + cg,       pB0);
                atomicAdd(g_agg + (size_t)(G0+1)*Hc + cg + 1,   pB1);
            }
        }
        if (h == 0) {
            CP_WAIT(0);
            __syncthreads();
        }
    }
}

// ---------------------------------------------------------------------------
// Node MLP: col-sliced warps, 8 row-accumulators/thread — weights read ONCE
// per block (was 8x). Reads + zeroes g_agg.
// ---------------------------------------------------------------------------
__global__ void __launch_bounds__(256) k_node(
    const float* __restrict__ Wo1, const float* __restrict__ bo1,
    const float* __restrict__ Wo2, const float* __restrict__ bo2,
    const float* __restrict__ Wo3, const float* __restrict__ bo3,
    float* __restrict__ out, int step)
{
    __shared__ float augS[8][264];
    __shared__ float h1S[8][264];
    __shared__ float lastS[8][4];
    __shared__ float wo3S[Hc*Dc];

    int tid = threadIdx.x;
    int wid = tid >> 5, lane = tid & 31;
    int base_row = blockIdx.x * 8;
    int c = wid*32 + lane;       // output column owned by this thread

    for (int i = tid; i < Hc*Dc; i += 256) wo3S[i] = Wo3[i];
    if (tid < 32) {
        int n = tid >> 2, d = tid & 3;
        float v = g_last[(base_row + n)*Dc + d];
        lastS[n][d] = v;
        augS[n][d]  = v;
    }
    {   // agg read + zero: warp wid owns row wid
        float* src = g_agg + (size_t)(base_row + wid)*Hc + lane*8;
        float4 v0 = *(float4*)src, v1 = *(float4*)(src + 4);
        *(float4*)(&augS[wid][4 + lane*8])     = v0;
        *(float4*)(&augS[wid][4 + lane*8 + 4]) = v1;
        float4 z = make_float4(0.f, 0.f, 0.f, 0.f);
        *(float4*)src = z; *(float4*)(src + 4) = z;
    }
    __syncthreads();

    // Layer 1: aug(8x260) @ Wo1 -> relu -> h1S; thread owns col c, 8 rows
    {
        float acc[8];
        #pragma unroll
        for (int r = 0; r < 8; r++) acc[r] = 0.f;
        #pragma unroll 4
        for (int j0 = 0; j0 < Dc + Hc; j0 += 4) {
            float4 av[8];
            #pragma unroll
            for (int r = 0; r < 8; r++) av[r] = *(const float4*)(&augS[r][j0]);
            float w0 = Wo1[(j0+0)*Hc + c];
            float w1 = Wo1[(j0+1)*Hc + c];
            float w2 = Wo1[(j0+2)*Hc + c];
            float w3 = Wo1[(j0+3)*Hc + c];
            #pragma unroll
            for (int r = 0; r < 8; r++)
                acc[r] += av[r].x*w0 + av[r].y*w1 + av[r].z*w2 + av[r].w*w3;
        }
        float bb = bo1[c];
        #pragma unroll
        for (int r = 0; r < 8; r++)
            h1S[r][c] = fmaxf(acc[r] + bb, 0.f);
    }
    __syncthreads();

    // Layer 2: h1(8x256) @ Wo2 -> relu -> augS[:,4..]
    {
        float acc[8];
        #pragma unroll
        for (int r = 0; r < 8; r++) acc[r] = 0.f;
        #pragma unroll 4
        for (int j0 = 0; j0 < Hc; j0 += 4) {
            float4 av[8];
            #pragma unroll
            for (int r = 0; r < 8; r++) av[r] = *(const float4*)(&h1S[r][j0]);
            float w0 = Wo2[(j0+0)*Hc + c];
            float w1 = Wo2[(j0+1)*Hc + c];
            float w2 = Wo2[(j0+2)*Hc + c];
            float w3 = Wo2[(j0+3)*Hc + c];
            #pragma unroll
            for (int r = 0; r < 8; r++)
                acc[r] += av[r].x*w0 + av[r].y*w1 + av[r].z*w2 + av[r].w*w3;
        }
        float bb = bo2[c];
        #pragma unroll
        for (int r = 0; r < 8; r++)
            augS[r][4 + c] = fmaxf(acc[r] + bb, 0.f);
    }
    __syncthreads();

    // Layer 3 (256->4) + residual + writes
    if (tid < 32) {
        int n = tid >> 2, d = tid & 3;
        float v = bo3[d];
        #pragma unroll 8
        for (int cc = 0; cc < Hc; cc++) v += augS[n][4 + cc] * wo3S[cc*Dc + d];
        float nl = lastS[n][d] + v;
        int grow = base_row + n;
        g_last[grow*Dc + d] = nl;
        int bt = grow >> 5, gn = grow & 31;
        int b = bt >> 3, tg = bt & 7;
        int t = tg*Pc + step;
        if (t < Tc - 1)
            out[((b*Nc + gn)*(Tc-1) + t)*Dc + d] = nl;
    }
}

// ---------------------------------------------------------------------------
extern "C" void kernel_launch(void* const* d_in, const int* in_sizes, int n_in,
                              void* d_out, int out_size)
{
    const float* inputs    = (const float*)d_in[0];
    const float* rel_graph = (const float*)d_in[1];
    const float* W1  = (const float*)d_in[2];
    const float* b1  = (const float*)d_in[3];
    const float* W2  = (const float*)d_in[4];
    const float* b2  = (const float*)d_in[5];
    const float* Wo1 = (const float*)d_in[6];
    const float* bo1 = (const float*)d_in[7];
    const float* Wo2 = (const float*)d_in[8];
    const float* bo2 = (const float*)d_in[9];
    const float* Wo3 = (const float*)d_in[10];
    const float* bo3 = (const float*)d_in[11];
    const float* gumbel = (const float*)d_in[14];
    float* out = (float*)d_out;

    cudaFuncSetAttribute(k_edge, cudaFuncAttributeMaxDynamicSharedMemorySize, SMEM_TOTAL);

    k_setup<<<64, 256>>>(rel_graph, gumbel, inputs, out);
    k_prep<<<64, 256>>>(W2, W1);
    for (int p = 0; p < Pc; p++) {
        k_edge<<<ROWS_E/128, 256, SMEM_TOTAL>>>(b1, b2, out, p);
        k_node<<<256, 256>>>(Wo1, bo1, Wo2, bo2, Wo3, bo3, out, p);
    }
}